// round 1
// baseline (speedup 1.0000x reference)
#include <cuda_runtime.h>

#define Nn 8
#define Hh 768
#define Ww 360
#define Dd 512
#define Cc (Ww*Nn)          // 2880 columns (w-major, n-minor)
#define PI_D 3.14159265358979323846

// ---------------- scratch (no allocation allowed) ----------------
__device__ float g_k[Hh];
__device__ float g_K[Hh*Hh];          // K[yp][y] = k[(y-yp) mod H]
__device__ float g_Rb[Cc*Hh];         // x-blended radon columns, [c][y']
__device__ float g_blend[Cc*Hh];      // filtered columns, [c][y]  (c = w*8+n)
__device__ float g_A[Ww];             // py = A*jr + B*ir + 383.5
__device__ float g_B[Ww];
__device__ int   g_x0[Ww];
__device__ int   g_x1[Ww];
__device__ float g_w0[Ww];
__device__ float g_w1[Ww];

// ---------------- stage A: k = real(ifft(h)) via double DFT ----------------
__global__ void compute_k_kernel(const float* __restrict__ hG) {
    int m = blockIdx.x;
    int t = threadIdx.x;
    double ang = 2.0 * PI_D * (double)m / (double)Hh;
    double acc = 0.0;
    for (int u = t; u < Hh; u += blockDim.x)
        acc += (double)hG[u] * cos(ang * (double)u);
    __shared__ double red[256];
    red[t] = acc;
    __syncthreads();
    for (int s = 128; s > 0; s >>= 1) {
        if (t < s) red[t] += red[t + s];
        __syncthreads();
    }
    if (t == 0) g_k[m] = (float)(red[0] / (double)Hh);
}

__global__ void fill_K_kernel() {
    int idx = blockIdx.x * blockDim.x + threadIdx.x;
    if (idx >= Hh * Hh) return;
    int yp = idx / Hh, y = idx - yp * Hh;
    int d = y - yp; if (d < 0) d += Hh;
    g_K[idx] = g_k[d];
}

// ---------------- stage B: per-angle params (replicates reference f32 math) ----------------
__global__ void params_kernel() {
    int w = threadIdx.x;
    if (w >= Ww) return;
    // theta: f32 like reference, trig in double (diff < 1e-7, negligible)
    float thf = __double2float_rn(PI_D / 180.0) * (0.5f * (float)w);
    double c = cos((double)thf), s = sin((double)thf);
    double sc = 383.5 / 384.0;  // sy / hH
    g_A[w] = (float)(c * sc);
    g_B[w] = (float)(-s * sc);
    // x interpolation: exact reference rounding order
    float step = __double2float_rn(2.0 / 359.0);
    float tx = -1.0f + (float)w * step;
    float px = (tx + 1.0f) * 179.5f;
    float x0f = floorf(px);
    float wx = px - x0f;
    int ix0 = (int)x0f, ix1 = ix0 + 1;
    float v0 = (ix0 >= 0 && ix0 < Ww) ? 1.0f : 0.0f;
    float v1 = (ix1 >= 0 && ix1 < Ww) ? 1.0f : 0.0f;
    g_w0[w] = (1.0f - wx) * v0;
    g_w1[w] = wx * v1;
    g_x0[w] = min(max(ix0, 0), Ww - 1);
    g_x1[w] = min(max(ix1, 0), Ww - 1);
}

// ---------------- stage C: x-blend radon columns into (w,n,y') layout ----------------
__global__ void rb_kernel(const float* __restrict__ radon) {
    int tid = blockIdx.x * blockDim.x + threadIdx.x;  // Cc*Hh threads
    int c = tid / Hh;
    int y = tid - c * Hh;
    int w = c >> 3;
    int n = c & 7;
    const float* row = radon + (n * Hh + y) * Ww;
    g_Rb[tid] = row[g_x0[w]] * g_w0[w] + row[g_x1[w]] * g_w1[w];
}

// ---------------- stage D: blend = Rb (2880x768) * K (768x768), fp32 SGEMM ----------------
__global__ void __launch_bounds__(256) sgemm_kernel() {
    __shared__ float As[16][64];   // [k][m]
    __shared__ float Bs[16][64];   // [k][n]
    int tid = threadIdx.x;
    int cCol = blockIdx.x;         // 12 tiles over y
    int cRow = blockIdx.y;         // 45 tiles over c
    int tCol = tid & 15;
    int tRow = tid >> 4;
    float acc[4][4] = {};

    int aRow = tid >> 2;           // 0..63
    int aCol = (tid & 3) * 4;      // 0,4,8,12
    int bRow = tid >> 4;           // 0..15
    int bCol = (tid & 15) * 4;

    const float* Ag = g_Rb + (cRow * 64 + aRow) * Hh + aCol;
    const float* Bg = g_K + bRow * Hh + cCol * 64 + bCol;

    for (int k0 = 0; k0 < Hh; k0 += 16) {
        float4 a = *(const float4*)(Ag + k0);
        float4 b = *(const float4*)(Bg + (size_t)k0 * Hh);
        As[aCol + 0][aRow] = a.x;
        As[aCol + 1][aRow] = a.y;
        As[aCol + 2][aRow] = a.z;
        As[aCol + 3][aRow] = a.w;
        *(float4*)&Bs[bRow][bCol] = b;
        __syncthreads();
#pragma unroll
        for (int k = 0; k < 16; k++) {
            float4 am = *(const float4*)&As[k][tRow * 4];
            float4 bn = *(const float4*)&Bs[k][tCol * 4];
            float amv[4] = {am.x, am.y, am.z, am.w};
            float bnv[4] = {bn.x, bn.y, bn.z, bn.w};
#pragma unroll
            for (int m = 0; m < 4; m++)
#pragma unroll
                for (int n = 0; n < 4; n++)
                    acc[m][n] = fmaf(amv[m], bnv[n], acc[m][n]);
        }
        __syncthreads();
    }
#pragma unroll
    for (int m = 0; m < 4; m++) {
        float4 v = make_float4(acc[m][0], acc[m][1], acc[m][2], acc[m][3]);
        *(float4*)&g_blend[(cRow * 64 + tRow * 4 + m) * Hh + cCol * 64 + tCol * 4] = v;
    }
}

// ---------------- stage E: backprojection ----------------
// block: 512 threads = (64 j) x (8 i-groups); each thread: 4 i's (stride 8) x 8 batches
// per angle: stage 24KB blend slice in smem (reg-prefetch double buffer), gather bilinear-y
__global__ void __launch_bounds__(512) backproj_kernel(float* __restrict__ out) {
    __shared__ float sh[Nn * Hh];       // [n][y], 24KB
    __shared__ float shA[Ww], shB[Ww];

    int tid = threadIdx.y * 64 + threadIdx.x;
    if (tid < Ww) { shA[tid] = g_A[tid]; shB[tid] = g_B[tid]; }

    int j = blockIdx.x * 64 + threadIdx.x;
    float jr = (float)(j - 256);
    int i0 = blockIdx.y * 32 + threadIdx.y;
    float ir[4];
#pragma unroll
    for (int r = 0; r < 4; r++) ir[r] = (float)(i0 + 8 * r - 256);

    float acc[4][8] = {};

    const float4* g4 = (const float4*)g_blend;
    float4 pf[3];
#pragma unroll
    for (int q = 0; q < 3; q++) pf[q] = g4[tid + q * 512];   // slice w=0 (1536 float4)

    for (int w = 0; w < Ww; w++) {
        __syncthreads();               // previous angle's reads done
        float4* s4 = (float4*)sh;
#pragma unroll
        for (int q = 0; q < 3; q++) s4[tid + q * 512] = pf[q];
        __syncthreads();
        if (w < Ww - 1) {
#pragma unroll
            for (int q = 0; q < 3; q++) pf[q] = g4[(w + 1) * 1536 + tid + q * 512];
        }
        float A = shA[w], B = shB[w];
        float base = fmaf(A, jr, 383.5f);
#pragma unroll
        for (int r = 0; r < 4; r++) {
            float py = fmaf(B, ir[r], base);      // always in [21.9, 745.1]
            int y0 = (int)py;
            float wy = py - (float)y0;
            float owy = 1.0f - wy;
            const float* s0 = sh + y0;
#pragma unroll
            for (int n = 0; n < 8; n++) {
                float v0 = s0[n * Hh];
                float v1 = s0[n * Hh + 1];
                acc[r][n] = fmaf(v0, owy, fmaf(v1, wy, acc[r][n]));
            }
        }
    }

    const float SC = (float)(PI_D / 720.0);       // pi / (2W)
#pragma unroll
    for (int r = 0; r < 4; r++) {
        int i = i0 + 8 * r;
#pragma unroll
        for (int n = 0; n < 8; n++)
            out[n * (Dd * Dd) + i * Dd + j] = acc[r][n] * SC;
    }
}

// ---------------- launch ----------------
extern "C" void kernel_launch(void* const* d_in, const int* in_sizes, int n_in,
                              void* d_out, int out_size) {
    (void)in_sizes; (void)n_in; (void)out_size;
    const float* radon = (const float*)d_in[0];
    const float* hG    = (const float*)d_in[1];
    float* out = (float*)d_out;

    compute_k_kernel<<<Hh, 256>>>(hG);
    fill_K_kernel<<<(Hh * Hh + 255) / 256, 256>>>();
    params_kernel<<<1, 384>>>();
    rb_kernel<<<(Cc * Hh) / 256, 256>>>(radon);
    sgemm_kernel<<<dim3(12, 45), 256>>>();
    backproj_kernel<<<dim3(8, 16), dim3(64, 8)>>>(out);
}

// round 3
// speedup vs baseline: 1.1758x; 1.1758x over previous
#include <cuda_runtime.h>
#include <cuda_fp16.h>

#define Nn 8
#define Hh 768
#define Ww 360
#define Dd 512
#define Cc (Ww*Nn)          // 2880 columns, c = w*8 + n
#define TAPS 257            // band: |d| <= 128
#define PI_D 3.14159265358979323846

// ---------------- scratch (no allocation allowed) ----------------
__device__ float g_kcp[264];                 // kcp[s] = k_signed(s-128), zero-padded to 264
__device__ float g_Rb[Cc*Hh];                // x-blended radon columns, [c][y]
__device__ __align__(16) __half g_blendh[Cc*Hh + 8];  // filtered columns fp16, [c][y] (+pad)
__device__ float g_A[Ww], g_B[Ww];
__device__ int   g_x0[Ww], g_x1[Ww];
__device__ float g_w0[Ww], g_w1[Ww];

// ---------------- stage A: banded filter taps via double DFT ----------------
__global__ void compute_kcp_kernel(const float* __restrict__ hG) {
    int m = blockIdx.x;          // 0..263
    int t = threadIdx.x;
    double acc = 0.0;
    if (m < TAPS) {
        double dd = (double)(m - 128);
        double ang = 2.0 * PI_D * dd / (double)Hh;
        for (int u = t; u < Hh; u += 256)
            acc += (double)hG[u] * cos(ang * (double)u);
    }
    __shared__ double red[256];
    red[t] = acc;
    __syncthreads();
    for (int s = 128; s > 0; s >>= 1) {
        if (t < s) red[t] += red[t + s];
        __syncthreads();
    }
    if (t == 0) g_kcp[m] = (m < TAPS) ? (float)(red[0] / (double)Hh) : 0.0f;
}

// ---------------- stage B: per-angle params (replicates reference f32 math) ----------------
__global__ void params_kernel() {
    int w = threadIdx.x;
    if (w >= Ww) return;
    float thf = __double2float_rn(PI_D / 180.0) * (0.5f * (float)w);
    double c = cos((double)thf), s = sin((double)thf);
    double sc = 383.5 / 384.0;
    g_A[w] = (float)(c * sc);
    g_B[w] = (float)(-s * sc);
    float step = __double2float_rn(2.0 / 359.0);
    float tx = -1.0f + (float)w * step;
    float px = (tx + 1.0f) * 179.5f;
    float x0f = floorf(px);
    float wx = px - x0f;
    int ix0 = (int)x0f, ix1 = ix0 + 1;
    float v0 = (ix0 >= 0 && ix0 < Ww) ? 1.0f : 0.0f;
    float v1 = (ix1 >= 0 && ix1 < Ww) ? 1.0f : 0.0f;
    g_w0[w] = (1.0f - wx) * v0;
    g_w1[w] = wx * v1;
    g_x0[w] = min(max(ix0, 0), Ww - 1);
    g_x1[w] = min(max(ix1, 0), Ww - 1);
}

// ---------------- stage C: x-blend radon columns into [c][y] ----------------
__global__ void rb_kernel(const float* __restrict__ radon) {
    int tid = blockIdx.x * blockDim.x + threadIdx.x;
    int c = tid / Hh;
    int y = tid - c * Hh;
    int w = c >> 3;
    int n = c & 7;
    const float* row = radon + (n * Hh + y) * Ww;
    g_Rb[tid] = row[g_x0[w]] * g_w0[w] + row[g_x1[w]] * g_w1[w];
}

// ---------------- stage D: 257-tap circular band conv along y, fp16 output ----------------
// block: 256 threads = 8 warps; tile = 32 cols x 64 y; lane = col, warp = 8 consecutive y
__global__ void __launch_bounds__(256) conv_kernel() {
    __shared__ float s[320][33];       // [u][col], u = yp - ytile + 128
    __shared__ float skc[264];
    int tid = threadIdx.x;
    int ctile = blockIdx.x * 32;
    int ytile = blockIdx.y * 64;

    // FIX (R2 bug): 264 taps, 256 threads -> strided load; tail was uninitialized smem
    for (int i = tid; i < 264; i += 256) skc[i] = g_kcp[i];

    // load window with circular wrap: 320 rows x 32 cols
    {
        int cloc = tid >> 3;
        int uoff = tid & 7;
        const float* src = g_Rb + (ctile + cloc) * Hh;
#pragma unroll
        for (int u = uoff; u < 320; u += 8) {
            int y = ytile + u - 128;
            if (y < 0) y += Hh; else if (y >= Hh) y -= Hh;
            s[u][cloc] = src[y];
        }
    }
    __syncthreads();

    int lane = tid & 31;
    int wi = tid >> 5;
    int y0 = wi << 3;

    float acc[8] = {};
    float k[8] = {};
#pragma unroll 8
    for (int ss = 0; ss < 264; ss++) {
        float w = s[y0 + ss][lane];
#pragma unroll
        for (int r = 7; r > 0; r--) k[r] = k[r - 1];
        k[0] = skc[ss];
#pragma unroll
        for (int r = 0; r < 8; r++) acc[r] = fmaf(w, k[r], acc[r]);
    }

    // write 8 consecutive y as fp16 (one 16B store)
    int cg = ctile + lane;
    __half2 h0 = __floats2half2_rn(acc[0], acc[1]);
    __half2 h1 = __floats2half2_rn(acc[2], acc[3]);
    __half2 h2 = __floats2half2_rn(acc[4], acc[5]);
    __half2 h3 = __floats2half2_rn(acc[6], acc[7]);
    uint4 val;
    val.x = *(unsigned int*)&h0;
    val.y = *(unsigned int*)&h1;
    val.z = *(unsigned int*)&h2;
    val.w = *(unsigned int*)&h3;
    *(uint4*)(g_blendh + (size_t)cg * Hh + ytile + y0) = val;
}

// ---------------- stage E: backprojection with fp16 pre-paired smem ----------------
// block (64,8)=512 thr; tile 64 j x 32 i; each thread 4 i (stride 8) x 8 batches
__global__ void __launch_bounds__(512) backproj_kernel(float* __restrict__ out) {
    __shared__ __align__(16) unsigned int ph[Nn * Hh];   // (v[y], v[y+1]) half2 per y
    __shared__ float shA[Ww], shB[Ww];

    int tid = threadIdx.y * 64 + threadIdx.x;
    if (tid < Ww) { shA[tid] = g_A[tid]; shB[tid] = g_B[tid]; }

    int j = blockIdx.x * 64 + threadIdx.x;
    float jr = (float)(j - 256);
    int i0 = blockIdx.y * 32 + threadIdx.y;
    float ir[4];
#pragma unroll
    for (int r = 0; r < 4; r++) ir[r] = (float)(i0 + 8 * r - 256);

    float acc[4][8] = {};

    const uint4* g16 = (const uint4*)g_blendh;          // 768 uint4 per angle slice
    const unsigned int* g4 = (const unsigned int*)g_blendh;

    int c0 = tid;            // chunk 0..511
    int c1 = tid + 512;      // chunk 512..767 (tid<256)
    uint4 rawA, rawB = make_uint4(0,0,0,0);
    unsigned int extA, extB = 0;
    rawA = g16[c0]; extA = g4[c0 * 4 + 4];
    if (c1 < 768) { rawB = g16[c1]; extB = g4[c1 * 4 + 4]; }

    for (int w = 0; w < Ww; w++) {
        __syncthreads();          // previous angle's reads complete
        {
            uint4 lo, hi;
            lo.x = rawA.x; lo.y = __funnelshift_r(rawA.x, rawA.y, 16);
            lo.z = rawA.y; lo.w = __funnelshift_r(rawA.y, rawA.z, 16);
            hi.x = rawA.z; hi.y = __funnelshift_r(rawA.z, rawA.w, 16);
            hi.z = rawA.w; hi.w = __funnelshift_r(rawA.w, extA, 16);
            *(uint4*)(ph + c0 * 8) = lo;
            *(uint4*)(ph + c0 * 8 + 4) = hi;
        }
        if (c1 < 768) {
            uint4 lo, hi;
            lo.x = rawB.x; lo.y = __funnelshift_r(rawB.x, rawB.y, 16);
            lo.z = rawB.y; lo.w = __funnelshift_r(rawB.y, rawB.z, 16);
            hi.x = rawB.z; hi.y = __funnelshift_r(rawB.z, rawB.w, 16);
            hi.z = rawB.w; hi.w = __funnelshift_r(rawB.w, extB, 16);
            *(uint4*)(ph + c1 * 8) = lo;
            *(uint4*)(ph + c1 * 8 + 4) = hi;
        }
        __syncthreads();
        if (w + 1 < Ww) {         // prefetch next slice into registers
            int b = (w + 1) * 768;
            rawA = g16[b + c0]; extA = g4[(b + c0) * 4 + 4];
            if (c1 < 768) { rawB = g16[b + c1]; extB = g4[(b + c1) * 4 + 4]; }
        }
        float A = shA[w], B = shB[w];
        float base = fmaf(A, jr, 383.5f);
#pragma unroll
        for (int r = 0; r < 4; r++) {
            float py = fmaf(B, ir[r], base);   // in [21.9, 745.1]
            int y0 = (int)py;
            float wy = py - (float)y0;
            float owy = 1.0f - wy;
            const unsigned int* pr = ph + y0;
#pragma unroll
            for (int n = 0; n < 8; n++) {
                unsigned int pv = pr[n * Hh];
                __half2 h = *(__half2*)&pv;
                float2 vf = __half22float2(h);
                acc[r][n] = fmaf(vf.x, owy, fmaf(vf.y, wy, acc[r][n]));
            }
        }
    }

    const float SC = (float)(PI_D / 720.0);   // pi / (2W)
#pragma unroll
    for (int r = 0; r < 4; r++) {
        int i = i0 + 8 * r;
#pragma unroll
        for (int n = 0; n < 8; n++)
            out[n * (Dd * Dd) + i * Dd + j] = acc[r][n] * SC;
    }
}

// ---------------- launch ----------------
extern "C" void kernel_launch(void* const* d_in, const int* in_sizes, int n_in,
                              void* d_out, int out_size) {
    (void)in_sizes; (void)n_in; (void)out_size;
    const float* radon = (const float*)d_in[0];
    const float* hG    = (const float*)d_in[1];
    float* out = (float*)d_out;

    compute_kcp_kernel<<<264, 256>>>(hG);
    params_kernel<<<1, 384>>>();
    rb_kernel<<<(Cc * Hh) / 256, 256>>>(radon);
    conv_kernel<<<dim3(90, 12), 256>>>();
    backproj_kernel<<<dim3(8, 16), dim3(64, 8)>>>(out);
}

// round 4
// speedup vs baseline: 1.6356x; 1.3911x over previous
#include <cuda_runtime.h>
#include <cuda_fp16.h>

#define Nn 8
#define Hh 768
#define Ww 360
#define Dd 512
#define Cc (Ww*Nn)          // 2880 columns, c = w*8 + n
#define TAPS 257            // band: |d| <= 128
#define PI_D 3.14159265358979323846

// ---------------- scratch (no allocation allowed) ----------------
__device__ float g_kcp[264];                 // kcp[s] = k_signed(s-128), zero-padded to 264
__device__ float g_Rb[Cc*Hh];                // x-blended radon columns, [c][y]
__device__ __align__(16) __half g_blend2[(size_t)Ww*Hh*Nn];  // filtered, [w][y][n] fp16
__device__ float g_A[Ww], g_B[Ww];
__device__ int   g_x0[Ww], g_x1[Ww];
__device__ float g_w0[Ww], g_w1[Ww];

// packed fp32x2 FMA (Blackwell)
#define FMA_F32X2(acc, d, k) asm("fma.rn.f32x2 %0, %1, %2, %0;" : "+l"(acc) : "l"(d), "l"(k))

// ---------------- stage A: banded filter taps via double DFT ----------------
__global__ void compute_kcp_kernel(const float* __restrict__ hG) {
    int m = blockIdx.x;          // 0..263
    int t = threadIdx.x;
    double acc = 0.0;
    if (m < TAPS) {
        double dd = (double)(m - 128);
        double ang = 2.0 * PI_D * dd / (double)Hh;
        for (int u = t; u < Hh; u += 256)
            acc += (double)hG[u] * cos(ang * (double)u);
    }
    __shared__ double red[256];
    red[t] = acc;
    __syncthreads();
    for (int s = 128; s > 0; s >>= 1) {
        if (t < s) red[t] += red[t + s];
        __syncthreads();
    }
    if (t == 0) g_kcp[m] = (m < TAPS) ? (float)(red[0] / (double)Hh) : 0.0f;
}

// ---------------- stage B: per-angle params (replicates reference f32 math) ----------------
__global__ void params_kernel() {
    int w = threadIdx.x;
    if (w >= Ww) return;
    float thf = __double2float_rn(PI_D / 180.0) * (0.5f * (float)w);
    double c = cos((double)thf), s = sin((double)thf);
    double sc = 383.5 / 384.0;
    g_A[w] = (float)(c * sc);
    g_B[w] = (float)(-s * sc);
    float step = __double2float_rn(2.0 / 359.0);
    float tx = -1.0f + (float)w * step;
    float px = (tx + 1.0f) * 179.5f;
    float x0f = floorf(px);
    float wx = px - x0f;
    int ix0 = (int)x0f, ix1 = ix0 + 1;
    float v0 = (ix0 >= 0 && ix0 < Ww) ? 1.0f : 0.0f;
    float v1 = (ix1 >= 0 && ix1 < Ww) ? 1.0f : 0.0f;
    g_w0[w] = (1.0f - wx) * v0;
    g_w1[w] = wx * v1;
    g_x0[w] = min(max(ix0, 0), Ww - 1);
    g_x1[w] = min(max(ix1, 0), Ww - 1);
}

// ---------------- stage C: x-blend radon columns into [c][y] ----------------
__global__ void rb_kernel(const float* __restrict__ radon) {
    int tid = blockIdx.x * blockDim.x + threadIdx.x;
    int c = tid / Hh;
    int y = tid - c * Hh;
    int w = c >> 3;
    int n = c & 7;
    const float* row = radon + (n * Hh + y) * Ww;
    g_Rb[tid] = row[g_x0[w]] * g_w0[w] + row[g_x1[w]] * g_w1[w];
}

// ---------------- stage D: 257-tap circular band conv, f32x2 packed, out [w][y][n] fp16 ----
// block: 256 thr; tile = 64 cols (8 w x 8 n) x 64 y; lane = col-pair (lane, lane+32)
// dynamic smem: s[320 rows][33 float2] + skc[264] + tb[8*528 halfs]
#define SROW 66                     // words per row (32 float2 + 1 pad float2)
#define TBW 528                     // halfs per w4 slice in transpose buf (64*8 + 16 pad)
__global__ void __launch_bounds__(256) conv_kernel() {
    extern __shared__ float dyn[];
    float* s = dyn;                          // 320*66 = 21120 words
    float* skc = dyn + 320 * SROW;           // 264 words
    __half* tb = (__half*)(skc + 264);       // 8*528 halfs = 8448 B

    int tid = threadIdx.x;
    int ctile = blockIdx.x * 64;
    int wtile = blockIdx.x * 8;
    int ytile = blockIdx.y * 64;

    for (int i = tid; i < 264; i += 256) skc[i] = g_kcp[i];

    // load window (circular wrap): 320 rows x (2x32) cols as float2
    {
        int cloc = tid >> 3;          // 0..31
        int uoff = tid & 7;
        const float* src0 = g_Rb + (ctile + cloc) * Hh;
        const float* src1 = g_Rb + (ctile + 32 + cloc) * Hh;
#pragma unroll
        for (int u = uoff; u < 320; u += 8) {
            int y = ytile + u - 128;
            if (y < 0) y += Hh; else if (y >= Hh) y -= Hh;
            s[u * SROW + cloc * 2]     = src0[y];
            s[u * SROW + cloc * 2 + 1] = src1[y];
        }
    }
    __syncthreads();

    int lane = tid & 31;
    int wi = tid >> 5;
    int y0 = wi << 3;

    unsigned long long a64[8] = {0,0,0,0,0,0,0,0};   // (col, col+32) fp32 pairs
    unsigned long long k2[8] = {0,0,0,0,0,0,0,0};    // broadcast tap pairs
    const float* srow = s + y0 * SROW + lane * 2;

#pragma unroll 8
    for (int ss = 0; ss < 264; ss++) {
        unsigned long long d = *(const unsigned long long*)(srow + ss * SROW);
#pragma unroll
        for (int r = 7; r > 0; r--) k2[r] = k2[r - 1];
        {
            unsigned int ki = __float_as_uint(skc[ss]);
            unsigned long long kn;
            asm("mov.b64 %0, {%1, %1};" : "=l"(kn) : "r"(ki));
            k2[0] = kn;
        }
#pragma unroll
        for (int r = 0; r < 8; r++) FMA_F32X2(a64[r], d, k2[r]);
    }

    // transpose to [w4][y][n] halfs in smem
    {
        int w4a = lane >> 3, nn = lane & 7;
        __half* pa = tb + w4a * TBW + y0 * 8 + nn;
        __half* pb = tb + (w4a + 4) * TBW + y0 * 8 + nn;
#pragma unroll
        for (int r = 0; r < 8; r++) {
            float2 f = *(float2*)&a64[r];
            pa[r * 8] = __float2half_rn(f.x);
            pb[r * 8] = __float2half_rn(f.y);
        }
    }
    __syncthreads();

    // coalesced uint4 writes: 512 rows (w4,y), 2 per thread
#pragma unroll
    for (int rr = tid; rr < 512; rr += 256) {
        int w4 = rr >> 6, yy = rr & 63;
        uint4 v = *(uint4*)(tb + w4 * TBW + yy * 8);
        *(uint4*)(g_blend2 + ((size_t)(wtile + w4) * Hh + ytile + yy) * 8) = v;
    }
}

// ---------------- stage E: backprojection, [y][n] rows + HFMA2 interpolation ----------------
// grid (8,32), block (64,4)=256 thr; tile 64 j x 16 i; thread: 4 i (stride 4) x 8 batches
__global__ void __launch_bounds__(256) backproj_kernel(float* __restrict__ out) {
    __shared__ __align__(16) uint4 ph2[Hh];     // row y: 8 batches fp16 (16B)
    __shared__ float shA[Ww], shB[Ww];

    int tid = threadIdx.y * 64 + threadIdx.x;
    for (int idx = tid; idx < Ww; idx += 256) { shA[idx] = g_A[idx]; shB[idx] = g_B[idx]; }

    int j = blockIdx.x * 64 + threadIdx.x;
    float jr = (float)(j - 256);
    int ibase = blockIdx.y * 16 + threadIdx.y;
    float ir[4];
#pragma unroll
    for (int r = 0; r < 4; r++) ir[r] = (float)(ibase + 4 * r - 256);

    float acc[4][8] = {};

    const uint4* g16 = (const uint4*)g_blend2;   // 768 uint4 per angle
    uint4 p0 = g16[tid];
    uint4 p1 = g16[tid + 256];
    uint4 p2 = g16[tid + 512];

    for (int w = 0; w < Ww; w++) {
        __syncthreads();              // previous angle's reads complete
        ph2[tid]       = p0;
        ph2[tid + 256] = p1;
        ph2[tid + 512] = p2;
        __syncthreads();
        if (w + 1 < Ww) {
            const uint4* nb = g16 + (w + 1) * Hh;
            p0 = nb[tid]; p1 = nb[tid + 256]; p2 = nb[tid + 512];
        }
        float A = shA[w], B = shB[w];
        float base = fmaf(A, jr, 383.5f);
#pragma unroll
        for (int r = 0; r < 4; r++) {
            float py = fmaf(B, ir[r], base);     // in [21.9, 745.1]
            int y0 = (int)py;
            float wy = py - (float)y0;
            __half2 hw1 = __float2half2_rn(wy);
            __half2 hw0 = __float2half2_rn(1.0f - wy);
            uint4 ra = ph2[y0];
            uint4 rb = ph2[y0 + 1];
            const unsigned int* au = (const unsigned int*)&ra;
            const unsigned int* bu = (const unsigned int*)&rb;
#pragma unroll
            for (int q = 0; q < 4; q++) {
                __half2 va = *(__half2*)&au[q];
                __half2 vb = *(__half2*)&bu[q];
                __half2 t = __hmul2(va, hw0);
                t = __hfma2(vb, hw1, t);
                float2 f = __half22float2(t);
                acc[r][2 * q]     += f.x;
                acc[r][2 * q + 1] += f.y;
            }
        }
    }

    const float SC = (float)(PI_D / 720.0);   // pi / (2W)
#pragma unroll
    for (int r = 0; r < 4; r++) {
        int i = ibase + 4 * r;
#pragma unroll
        for (int n = 0; n < 8; n++)
            out[n * (Dd * Dd) + i * Dd + j] = acc[r][n] * SC;
    }
}

// ---------------- launch ----------------
extern "C" void kernel_launch(void* const* d_in, const int* in_sizes, int n_in,
                              void* d_out, int out_size) {
    (void)in_sizes; (void)n_in; (void)out_size;
    const float* radon = (const float*)d_in[0];
    const float* hG    = (const float*)d_in[1];
    float* out = (float*)d_out;

    const int conv_smem = (320 * SROW + 264) * 4 + 8 * TBW * 2;   // 93,984 B
    cudaFuncSetAttribute(conv_kernel, cudaFuncAttributeMaxDynamicSharedMemorySize, conv_smem);

    compute_kcp_kernel<<<264, 256>>>(hG);
    params_kernel<<<1, 384>>>();
    rb_kernel<<<(Cc * Hh) / 256, 256>>>(radon);
    conv_kernel<<<dim3(45, 12), 256, conv_smem>>>();
    backproj_kernel<<<dim3(8, 32), dim3(64, 4)>>>(out);
}

// round 5
// speedup vs baseline: 1.7927x; 1.0961x over previous
#include <cuda_runtime.h>
#include <cuda_fp16.h>

#define Nn 8
#define Hh 768
#define Ww 360
#define Dd 512
#define Cc (Ww*Nn)          // 2880 columns, c = w*8 + n
#define TAPS 257            // band: |d| <= 128
#define PI_D 3.14159265358979323846

// ---------------- scratch (no allocation allowed) ----------------
__device__ float g_kcp[264];                 // kcp[s] = k_signed(s-128), zero-padded to 264
__device__ float g_Rb[Cc*Hh];                // x-blended radon columns, [c][y]
__device__ __align__(16) __half g_blend2[(size_t)Ww*Hh*Nn];  // filtered, [w][y][n] fp16
__device__ float g_A[Ww], g_B[Ww];
__device__ int   g_x0[Ww], g_x1[Ww];
__device__ float g_w0[Ww], g_w1[Ww];

// packed fp32x2 FMA (Blackwell)
#define FMA_F32X2(acc, d, k) asm("fma.rn.f32x2 %0, %1, %2, %0;" : "+l"(acc) : "l"(d), "l"(k))

// ---------------- stage A: banded filter taps via double DFT ----------------
__global__ void compute_kcp_kernel(const float* __restrict__ hG) {
    int m = blockIdx.x;          // 0..263
    int t = threadIdx.x;
    double acc = 0.0;
    if (m < TAPS) {
        double dd = (double)(m - 128);
        double ang = 2.0 * PI_D * dd / (double)Hh;
        for (int u = t; u < Hh; u += 256)
            acc += (double)hG[u] * cos(ang * (double)u);
    }
    __shared__ double red[256];
    red[t] = acc;
    __syncthreads();
    for (int s = 128; s > 0; s >>= 1) {
        if (t < s) red[t] += red[t + s];
        __syncthreads();
    }
    if (t == 0) g_kcp[m] = (m < TAPS) ? (float)(red[0] / (double)Hh) : 0.0f;
}

// ---------------- stage B: per-angle params (replicates reference f32 math) ----------------
__global__ void params_kernel() {
    int w = threadIdx.x;
    if (w >= Ww) return;
    float thf = __double2float_rn(PI_D / 180.0) * (0.5f * (float)w);
    double c = cos((double)thf), s = sin((double)thf);
    double sc = 383.5 / 384.0;
    g_A[w] = (float)(c * sc);
    g_B[w] = (float)(-s * sc);
    float step = __double2float_rn(2.0 / 359.0);
    float tx = -1.0f + (float)w * step;
    float px = (tx + 1.0f) * 179.5f;
    float x0f = floorf(px);
    float wx = px - x0f;
    int ix0 = (int)x0f, ix1 = ix0 + 1;
    float v0 = (ix0 >= 0 && ix0 < Ww) ? 1.0f : 0.0f;
    float v1 = (ix1 >= 0 && ix1 < Ww) ? 1.0f : 0.0f;
    g_w0[w] = (1.0f - wx) * v0;
    g_w1[w] = wx * v1;
    g_x0[w] = min(max(ix0, 0), Ww - 1);
    g_x1[w] = min(max(ix1, 0), Ww - 1);
}

// ---------------- stage C: x-blend radon columns into [c][y] ----------------
__global__ void rb_kernel(const float* __restrict__ radon) {
    int tid = blockIdx.x * blockDim.x + threadIdx.x;
    int c = tid / Hh;
    int y = tid - c * Hh;
    int w = c >> 3;
    int n = c & 7;
    const float* row = radon + (n * Hh + y) * Ww;
    g_Rb[tid] = row[g_x0[w]] * g_w0[w] + row[g_x1[w]] * g_w1[w];
}

// ---------------- stage D: 257-tap circular band conv, fp16 window, f32x2 FMA ----------
// block: 256 thr; tile = 64 cols (8 w x 8 n) x 64 y; lane = col-pair (lane, lane+32)
#define SROW 33                     // half2 words per window row (32 + 1 pad)
#define TBW 528                     // halfs per w4 slice in transpose buf (64*8 + 16 pad)
__global__ void __launch_bounds__(256, 4) conv_kernel() {
    extern __shared__ float dyn[];
    unsigned int* sw = (unsigned int*)dyn;       // 320*33 half2 words = 42240 B
    float* skc = dyn + 320 * SROW;               // 264 words
    __half* tb = (__half*)(skc + 264);           // 8*528 halfs = 8448 B

    int tid = threadIdx.x;
    int ctile = blockIdx.x * 64;
    int wtile = blockIdx.x * 8;
    int ytile = blockIdx.y * 64;

    for (int i = tid; i < 264; i += 256) skc[i] = g_kcp[i];

    // load window (circular wrap): 320 rows x 32 col-pairs, fp16
    {
        int cloc = tid >> 3;          // 0..31
        int uoff = tid & 7;
        const float* src0 = g_Rb + (ctile + cloc) * Hh;
        const float* src1 = g_Rb + (ctile + 32 + cloc) * Hh;
#pragma unroll
        for (int u = uoff; u < 320; u += 8) {
            int y = ytile + u - 128;
            if (y < 0) y += Hh; else if (y >= Hh) y -= Hh;
            __half2 hv = __floats2half2_rn(src0[y], src1[y]);
            sw[u * SROW + cloc] = *(unsigned int*)&hv;
        }
    }
    __syncthreads();

    int lane = tid & 31;
    int wi = tid >> 5;
    int y0 = wi << 3;

    unsigned long long a64[8] = {0,0,0,0,0,0,0,0};   // (col, col+32) fp32 pairs
    unsigned long long k2[8] = {0,0,0,0,0,0,0,0};
    const unsigned int* srow = sw + y0 * SROW + lane;

#pragma unroll 8
    for (int ss = 0; ss < 264; ss++) {
        unsigned int hd = srow[ss * SROW];
        __half2 h = *(__half2*)&hd;
        float2 f = __half22float2(h);
        unsigned long long d;
        asm("mov.b64 %0, {%1, %2};" : "=l"(d) : "f"(f.x), "f"(f.y));
#pragma unroll
        for (int r = 7; r > 0; r--) k2[r] = k2[r - 1];
        {
            unsigned int ki = __float_as_uint(skc[ss]);
            unsigned long long kn;
            asm("mov.b64 %0, {%1, %1};" : "=l"(kn) : "r"(ki));
            k2[0] = kn;
        }
#pragma unroll
        for (int r = 0; r < 8; r++) FMA_F32X2(a64[r], d, k2[r]);
    }

    // transpose to [w4][y][n] halfs in smem
    {
        int w4a = lane >> 3, nn = lane & 7;
        __half* pa = tb + w4a * TBW + y0 * 8 + nn;
        __half* pb = tb + (w4a + 4) * TBW + y0 * 8 + nn;
#pragma unroll
        for (int r = 0; r < 8; r++) {
            float2 f = *(float2*)&a64[r];
            pa[r * 8] = __float2half_rn(f.x);
            pb[r * 8] = __float2half_rn(f.y);
        }
    }
    __syncthreads();

    // coalesced uint4 writes: 512 rows (w4,y), 2 per thread
#pragma unroll
    for (int rr = tid; rr < 512; rr += 256) {
        int w4 = rr >> 6, yy = rr & 63;
        uint4 v = *(uint4*)(tb + w4 * TBW + yy * 8);
        *(uint4*)(g_blend2 + ((size_t)(wtile + w4) * Hh + ytile + yy) * 8) = v;
    }
}

// ---------------- stage E: backprojection ----------------
// grid (16,16), block 256 (1D). Block tile 32j x 32i. Warp footprint 8j x 4i (py span < 8
// => conflict-free LDS.128). Ping-pong 2-angle smem buffers: 1 sync per 2 angles.
__global__ void __launch_bounds__(256, 2) backproj_kernel(float* __restrict__ out) {
    __shared__ __align__(16) uint4 ph[4 * Hh];    // 2 bufs x 2 angles x 768 rows = 49KB
    __shared__ float shA[Ww], shB[Ww];

    int tid = threadIdx.x;
    for (int idx = tid; idx < Ww; idx += 256) { shA[idx] = g_A[idx]; shB[idx] = g_B[idx]; }

    int warp = tid >> 5, lane = tid & 31;
    int lj = lane & 7, li = lane >> 3;       // 8 x 4 warp footprint
    int jgrp = warp & 3, igrp = warp >> 2;
    int j = blockIdx.x * 32 + jgrp * 8 + lj;
    float jr = (float)(j - 256);
    int i_base = blockIdx.y * 32 + igrp * 16 + li;
    float ir[4];
#pragma unroll
    for (int r = 0; r < 4; r++) ir[r] = (float)(i_base + 4 * r - 256);

    const uint4* g16 = (const uint4*)g_blend2;    // 768 uint4 per angle
    uint4 pf[6];
#pragma unroll
    for (int k = 0; k < 6; k++) pf[k] = g16[tid + 256 * k];      // slices 0,1
#pragma unroll
    for (int k = 0; k < 6; k++) ph[tid + 256 * k] = pf[k];       // -> buf 0
    __syncthreads();

    float acc[4][8] = {};
    __half2 hones = __float2half2_rn(1.0f);

    for (int rnd = 0; rnd < 180; rnd++) {
        if (rnd + 1 < 180) {                     // prefetch next 2 slices
            const uint4* src = g16 + (2 * (rnd + 1)) * Hh;
#pragma unroll
            for (int k = 0; k < 6; k++) pf[k] = src[tid + 256 * k];
        }
        const uint4* bufp = ph + (rnd & 1) * (2 * Hh);
#pragma unroll
        for (int h = 0; h < 2; h++) {
            int a = 2 * rnd + h;
            float A = shA[a], B = shB[a];
            float base = fmaf(A, jr, 383.5f);
            const uint4* rows = bufp + h * Hh;
#pragma unroll
            for (int r = 0; r < 4; r++) {
                float py = fmaf(B, ir[r], base);   // in [21.9, 745.1]
                int y0 = (int)py;
                float wy = py - (float)y0;
                __half2 hw1 = __float2half2_rn(wy);
                __half2 hw0 = __hsub2(hones, hw1);
                uint4 ra = rows[y0];
                uint4 rb = rows[y0 + 1];
                const unsigned int* au = (const unsigned int*)&ra;
                const unsigned int* bu = (const unsigned int*)&rb;
#pragma unroll
                for (int q = 0; q < 4; q++) {
                    __half2 va = *(__half2*)&au[q];
                    __half2 vb = *(__half2*)&bu[q];
                    __half2 t = __hmul2(va, hw0);
                    t = __hfma2(vb, hw1, t);
                    float2 f = __half22float2(t);
                    acc[r][2 * q]     += f.x;
                    acc[r][2 * q + 1] += f.y;
                }
            }
        }
        if (rnd + 1 < 180) {                     // stage into the other buffer
            uint4* dst = ph + ((rnd + 1) & 1) * (2 * Hh);
#pragma unroll
            for (int k = 0; k < 6; k++) dst[tid + 256 * k] = pf[k];
        }
        __syncthreads();
    }

    const float SC = (float)(PI_D / 720.0);   // pi / (2W)
#pragma unroll
    for (int r = 0; r < 4; r++) {
        int i = i_base + 4 * r;
#pragma unroll
        for (int n = 0; n < 8; n++)
            out[n * (Dd * Dd) + i * Dd + j] = acc[r][n] * SC;
    }
}

// ---------------- launch ----------------
extern "C" void kernel_launch(void* const* d_in, const int* in_sizes, int n_in,
                              void* d_out, int out_size) {
    (void)in_sizes; (void)n_in; (void)out_size;
    const float* radon = (const float*)d_in[0];
    const float* hG    = (const float*)d_in[1];
    float* out = (float*)d_out;

    const int conv_smem = 320 * SROW * 4 + 264 * 4 + 8 * TBW * 2;   // 51,744 B
    cudaFuncSetAttribute(conv_kernel, cudaFuncAttributeMaxDynamicSharedMemorySize, conv_smem);

    compute_kcp_kernel<<<264, 256>>>(hG);
    params_kernel<<<1, 384>>>();
    rb_kernel<<<(Cc * Hh) / 256, 256>>>(radon);
    conv_kernel<<<dim3(45, 12), 256, conv_smem>>>();
    backproj_kernel<<<dim3(16, 16), 256>>>(out);
}

// round 6
// speedup vs baseline: 1.8649x; 1.0403x over previous
#include <cuda_runtime.h>
#include <cuda_fp16.h>

#define Nn 8
#define Hh 768
#define Ww 360
#define Dd 512
#define Cc (Ww*Nn)          // 2880 columns, c = w*8 + n
#define TAPS 257            // band: |d| <= 128
#define PI_D 3.14159265358979323846

// ---------------- scratch (no allocation allowed) ----------------
__device__ float g_kcp[264];                 // kcp[s] = k_signed(s-128), zero-padded to 264
__device__ float g_Rb[Cc*Hh];                // x-blended radon columns, [c][y]
__device__ __align__(16) __half g_blend2[(size_t)Ww*Hh*Nn];  // filtered, [w][y][n] fp16
__device__ float g_A[Ww], g_B[Ww];
__device__ int   g_x0[Ww], g_x1[Ww];
__device__ float g_w0[Ww], g_w1[Ww];

// packed fp32x2 FMA (Blackwell)
#define FMA_F32X2(acc, d, k) asm("fma.rn.f32x2 %0, %1, %2, %0;" : "+l"(acc) : "l"(d), "l"(k))

// ---------------- stage A: banded filter taps via double DFT ----------------
__global__ void compute_kcp_kernel(const float* __restrict__ hG) {
    int m = blockIdx.x;          // 0..263
    int t = threadIdx.x;
    double acc = 0.0;
    if (m < TAPS) {
        double dd = (double)(m - 128);
        double ang = 2.0 * PI_D * dd / (double)Hh;
        for (int u = t; u < Hh; u += 256)
            acc += (double)hG[u] * cos(ang * (double)u);
    }
    __shared__ double red[256];
    red[t] = acc;
    __syncthreads();
    for (int s = 128; s > 0; s >>= 1) {
        if (t < s) red[t] += red[t + s];
        __syncthreads();
    }
    if (t == 0) g_kcp[m] = (m < TAPS) ? (float)(red[0] / (double)Hh) : 0.0f;
}

// ---------------- stage B: per-angle params (replicates reference f32 math) ----------------
__global__ void params_kernel() {
    int w = threadIdx.x;
    if (w >= Ww) return;
    float thf = __double2float_rn(PI_D / 180.0) * (0.5f * (float)w);
    double c = cos((double)thf), s = sin((double)thf);
    double sc = 383.5 / 384.0;
    g_A[w] = (float)(c * sc);
    g_B[w] = (float)(-s * sc);
    float step = __double2float_rn(2.0 / 359.0);
    float tx = -1.0f + (float)w * step;
    float px = (tx + 1.0f) * 179.5f;
    float x0f = floorf(px);
    float wx = px - x0f;
    int ix0 = (int)x0f, ix1 = ix0 + 1;
    float v0 = (ix0 >= 0 && ix0 < Ww) ? 1.0f : 0.0f;
    float v1 = (ix1 >= 0 && ix1 < Ww) ? 1.0f : 0.0f;
    g_w0[w] = (1.0f - wx) * v0;
    g_w1[w] = wx * v1;
    g_x0[w] = min(max(ix0, 0), Ww - 1);
    g_x1[w] = min(max(ix1, 0), Ww - 1);
}

// ---------------- stage C: x-blend, smem-tiled (coalesced in AND out) ----------------
// grid (24, 8): blockIdx.x = 32-y tile, blockIdx.y = n. lane = y, warp-uniform w.
__global__ void __launch_bounds__(256) rb_kernel(const float* __restrict__ radon) {
    __shared__ float sm[32 * 361];     // stride 361: y*361+x -> banks y*9+x, conflict-free
    int n = blockIdx.y;
    int yt = blockIdx.x * 32;
    int tid = threadIdx.x;
    const float* src = radon + ((size_t)n * Hh + yt) * Ww;
#pragma unroll
    for (int idx = tid; idx < 32 * Ww; idx += 256) {
        int y = idx / Ww, x = idx - y * Ww;
        sm[y * 361 + x] = src[y * Ww + x];
    }
    __syncthreads();
#pragma unroll
    for (int idx = tid; idx < Ww * 32; idx += 256) {
        int w = idx >> 5, y = idx & 31;
        float v = sm[y * 361 + g_x0[w]] * g_w0[w] + sm[y * 361 + g_x1[w]] * g_w1[w];
        g_Rb[(size_t)(w * 8 + n) * Hh + yt + y] = v;
    }
}

// ---------------- stage D: 257-tap circular band conv, f32x2 packed, out [w][y][n] fp16 ----
// (R4 version, proven 35.8us) block: 256 thr; tile 64 cols x 64 y; lane = col-pair
#define SROW 66                     // words per row (32 float2 + 1 pad float2)
#define TBW 528                     // halfs per w4 slice in transpose buf (64*8 + 16 pad)
__global__ void __launch_bounds__(256) conv_kernel() {
    extern __shared__ float dyn[];
    float* s = dyn;                          // 320*66 words
    float* skc = dyn + 320 * SROW;           // 264 words
    __half* tb = (__half*)(skc + 264);       // 8*528 halfs

    int tid = threadIdx.x;
    int ctile = blockIdx.x * 64;
    int wtile = blockIdx.x * 8;
    int ytile = blockIdx.y * 64;

    for (int i = tid; i < 264; i += 256) skc[i] = g_kcp[i];

    {
        int cloc = tid >> 3;
        int uoff = tid & 7;
        const float* src0 = g_Rb + (ctile + cloc) * Hh;
        const float* src1 = g_Rb + (ctile + 32 + cloc) * Hh;
#pragma unroll
        for (int u = uoff; u < 320; u += 8) {
            int y = ytile + u - 128;
            if (y < 0) y += Hh; else if (y >= Hh) y -= Hh;
            s[u * SROW + cloc * 2]     = src0[y];
            s[u * SROW + cloc * 2 + 1] = src1[y];
        }
    }
    __syncthreads();

    int lane = tid & 31;
    int wi = tid >> 5;
    int y0 = wi << 3;

    unsigned long long a64[8] = {0,0,0,0,0,0,0,0};
    unsigned long long k2[8] = {0,0,0,0,0,0,0,0};
    const float* srow = s + y0 * SROW + lane * 2;

#pragma unroll 8
    for (int ss = 0; ss < 264; ss++) {
        unsigned long long d = *(const unsigned long long*)(srow + ss * SROW);
#pragma unroll
        for (int r = 7; r > 0; r--) k2[r] = k2[r - 1];
        {
            unsigned int ki = __float_as_uint(skc[ss]);
            unsigned long long kn;
            asm("mov.b64 %0, {%1, %1};" : "=l"(kn) : "r"(ki));
            k2[0] = kn;
        }
#pragma unroll
        for (int r = 0; r < 8; r++) FMA_F32X2(a64[r], d, k2[r]);
    }

    {
        int w4a = lane >> 3, nn = lane & 7;
        __half* pa = tb + w4a * TBW + y0 * 8 + nn;
        __half* pb = tb + (w4a + 4) * TBW + y0 * 8 + nn;
#pragma unroll
        for (int r = 0; r < 8; r++) {
            float2 f = *(float2*)&a64[r];
            pa[r * 8] = __float2half_rn(f.x);
            pb[r * 8] = __float2half_rn(f.y);
        }
    }
    __syncthreads();

#pragma unroll
    for (int rr = tid; rr < 512; rr += 256) {
        int w4 = rr >> 6, yy = rr & 63;
        uint4 v = *(uint4*)(tb + w4 * TBW + yy * 8);
        *(uint4*)(g_blend2 + ((size_t)(wtile + w4) * Hh + ytile + yy) * 8) = v;
    }
}

// ---------------- stage E: backprojection, half2 8-angle partial accumulation ----------------
// grid (16,16), block 256. Warp footprint 8j x 4i (py span < 8 => conflict-free LDS.128).
// Ping-pong 2-angle buffers, 1 sync / 2 angles. Inner loop: 2 HFMA2 per q, NO conversions.
__global__ void __launch_bounds__(256, 2) backproj_kernel(float* __restrict__ out) {
    __shared__ __align__(16) uint4 ph[4 * Hh];    // 2 bufs x 2 angles x 768 rows = 49KB
    __shared__ float shA[Ww], shB[Ww];

    int tid = threadIdx.x;
    for (int idx = tid; idx < Ww; idx += 256) { shA[idx] = g_A[idx]; shB[idx] = g_B[idx]; }

    int warp = tid >> 5, lane = tid & 31;
    int lj = lane & 7, li = lane >> 3;
    int jgrp = warp & 3, igrp = warp >> 2;
    int j = blockIdx.x * 32 + jgrp * 8 + lj;
    float jr = (float)(j - 256);
    int i_base = blockIdx.y * 32 + igrp * 16 + li;
    float ir[4];
#pragma unroll
    for (int r = 0; r < 4; r++) ir[r] = (float)(i_base + 4 * r - 256);

    const uint4* g16 = (const uint4*)g_blend2;
    uint4 pf[6];
#pragma unroll
    for (int k = 0; k < 6; k++) pf[k] = g16[tid + 256 * k];
#pragma unroll
    for (int k = 0; k < 6; k++) ph[tid + 256 * k] = pf[k];
    __syncthreads();

    float acc[4][8] = {};
    __half2 hones = __float2half2_rn(1.0f);

    for (int g = 0; g < 45; g++) {            // 45 groups x 8 angles
        __half2 pacc[4][4];
#pragma unroll
        for (int r = 0; r < 4; r++)
#pragma unroll
            for (int q = 0; q < 4; q++) pacc[r][q] = __float2half2_rn(0.0f);

#pragma unroll
        for (int r4 = 0; r4 < 4; r4++) {
            int rnd = g * 4 + r4;
            if (rnd + 1 < 180) {
                const uint4* src = g16 + (2 * (rnd + 1)) * Hh;
#pragma unroll
                for (int k = 0; k < 6; k++) pf[k] = src[tid + 256 * k];
            }
            const uint4* bufp = ph + (rnd & 1) * (2 * Hh);
#pragma unroll
            for (int h = 0; h < 2; h++) {
                int a = 2 * rnd + h;
                float A = shA[a], B = shB[a];
                float base = fmaf(A, jr, 383.5f);
                const uint4* rows = bufp + h * Hh;
#pragma unroll
                for (int r = 0; r < 4; r++) {
                    float py = fmaf(B, ir[r], base);   // in [21.9, 745.1]
                    int y0 = (int)py;
                    float wy = py - (float)y0;
                    __half2 hw1 = __float2half2_rn(wy);
                    __half2 hw0 = __hsub2(hones, hw1);
                    uint4 ra = rows[y0];
                    uint4 rb = rows[y0 + 1];
                    const unsigned int* au = (const unsigned int*)&ra;
                    const unsigned int* bu = (const unsigned int*)&rb;
#pragma unroll
                    for (int q = 0; q < 4; q++) {
                        __half2 va = *(__half2*)&au[q];
                        __half2 vb = *(__half2*)&bu[q];
                        pacc[r][q] = __hfma2(va, hw0, pacc[r][q]);
                        pacc[r][q] = __hfma2(vb, hw1, pacc[r][q]);
                    }
                }
            }
            if (rnd + 1 < 180) {
                uint4* dst = ph + ((rnd + 1) & 1) * (2 * Hh);
#pragma unroll
                for (int k = 0; k < 6; k++) dst[tid + 256 * k] = pf[k];
            }
            __syncthreads();
        }

        // flush 8-angle half2 partials into fp32 accumulators
#pragma unroll
        for (int r = 0; r < 4; r++)
#pragma unroll
            for (int q = 0; q < 4; q++) {
                float2 f = __half22float2(pacc[r][q]);
                acc[r][2 * q]     += f.x;
                acc[r][2 * q + 1] += f.y;
            }
    }

    const float SC = (float)(PI_D / 720.0);   // pi / (2W)
#pragma unroll
    for (int r = 0; r < 4; r++) {
        int i = i_base + 4 * r;
#pragma unroll
        for (int n = 0; n < 8; n++)
            out[n * (Dd * Dd) + i * Dd + j] = acc[r][n] * SC;
    }
}

// ---------------- launch ----------------
extern "C" void kernel_launch(void* const* d_in, const int* in_sizes, int n_in,
                              void* d_out, int out_size) {
    (void)in_sizes; (void)n_in; (void)out_size;
    const float* radon = (const float*)d_in[0];
    const float* hG    = (const float*)d_in[1];
    float* out = (float*)d_out;

    const int conv_smem = (320 * SROW + 264) * 4 + 8 * TBW * 2;   // 93,984 B
    cudaFuncSetAttribute(conv_kernel, cudaFuncAttributeMaxDynamicSharedMemorySize, conv_smem);

    compute_kcp_kernel<<<264, 256>>>(hG);
    params_kernel<<<1, 384>>>();
    rb_kernel<<<dim3(24, 8), 256>>>(radon);
    conv_kernel<<<dim3(45, 12), 256, conv_smem>>>();
    backproj_kernel<<<dim3(16, 16), 256>>>(out);
}

// round 7
// speedup vs baseline: 1.8959x; 1.0166x over previous
#include <cuda_runtime.h>
#include <cuda_fp16.h>

#define Nn 8
#define Hh 768
#define Ww 360
#define Dd 512
#define Cc (Ww*Nn)          // 2880 columns, c = w*8 + n
#define TAPS 257            // band: |d| <= 128
#define PI_D 3.14159265358979323846

// ---------------- scratch (no allocation allowed) ----------------
__device__ float g_kcp[264];                 // kcp[s] = k_signed(s-128), zero-padded to 264
__device__ float g_Rb[Cc*Hh];                // x-blended radon columns, [c][y]
__device__ __align__(16) __half g_blend2[(size_t)Ww*Hh*Nn];  // filtered, [w][y][n] fp16
__device__ float g_A[Ww], g_B[Ww];
__device__ int   g_x0[Ww], g_x1[Ww];
__device__ float g_w0[Ww], g_w1[Ww];

// packed fp32x2 FMA (Blackwell)
#define FMA_F32X2(acc, d, k) asm("fma.rn.f32x2 %0, %1, %2, %0;" : "+l"(acc) : "l"(d), "l"(k))

// ---------------- stage A: banded filter taps via double DFT ----------------
__global__ void compute_kcp_kernel(const float* __restrict__ hG) {
    int m = blockIdx.x;          // 0..263
    int t = threadIdx.x;
    double acc = 0.0;
    if (m < TAPS) {
        double dd = (double)(m - 128);
        double ang = 2.0 * PI_D * dd / (double)Hh;
        for (int u = t; u < Hh; u += 256)
            acc += (double)hG[u] * cos(ang * (double)u);
    }
    __shared__ double red[256];
    red[t] = acc;
    __syncthreads();
    for (int s = 128; s > 0; s >>= 1) {
        if (t < s) red[t] += red[t + s];
        __syncthreads();
    }
    if (t == 0) g_kcp[m] = (m < TAPS) ? (float)(red[0] / (double)Hh) : 0.0f;
}

// ---------------- stage B: per-angle params (replicates reference f32 math) ----------------
__global__ void params_kernel() {
    int w = threadIdx.x;
    if (w >= Ww) return;
    float thf = __double2float_rn(PI_D / 180.0) * (0.5f * (float)w);
    double c = cos((double)thf), s = sin((double)thf);
    double sc = 383.5 / 384.0;
    g_A[w] = (float)(c * sc);
    g_B[w] = (float)(-s * sc);
    float step = __double2float_rn(2.0 / 359.0);
    float tx = -1.0f + (float)w * step;
    float px = (tx + 1.0f) * 179.5f;
    float x0f = floorf(px);
    float wx = px - x0f;
    int ix0 = (int)x0f, ix1 = ix0 + 1;
    float v0 = (ix0 >= 0 && ix0 < Ww) ? 1.0f : 0.0f;
    float v1 = (ix1 >= 0 && ix1 < Ww) ? 1.0f : 0.0f;
    g_w0[w] = (1.0f - wx) * v0;
    g_w1[w] = wx * v1;
    g_x0[w] = min(max(ix0, 0), Ww - 1);
    g_x1[w] = min(max(ix1, 0), Ww - 1);
}

// ---------------- stage C: x-blend, smem-tiled (coalesced in AND out) ----------------
__global__ void __launch_bounds__(256) rb_kernel(const float* __restrict__ radon) {
    __shared__ float sm[32 * 361];     // stride 361: conflict-free
    int n = blockIdx.y;
    int yt = blockIdx.x * 32;
    int tid = threadIdx.x;
    const float* src = radon + ((size_t)n * Hh + yt) * Ww;
#pragma unroll
    for (int idx = tid; idx < 32 * Ww; idx += 256) {
        int y = idx / Ww, x = idx - y * Ww;
        sm[y * 361 + x] = src[y * Ww + x];
    }
    __syncthreads();
#pragma unroll
    for (int idx = tid; idx < Ww * 32; idx += 256) {
        int w = idx >> 5, y = idx & 31;
        float v = sm[y * 361 + g_x0[w]] * g_w0[w] + sm[y * 361 + g_x1[w]] * g_w1[w];
        g_Rb[(size_t)(w * 8 + n) * Hh + yt + y] = v;
    }
}

// ---------------- stage D: 257-tap circular band conv (R4 version, proven) ----------
#define SROW 66                     // words per row (32 float2 + 1 pad float2)
#define TBW 528                     // halfs per w4 slice in transpose buf
__global__ void __launch_bounds__(256) conv_kernel() {
    extern __shared__ float dyn[];
    float* s = dyn;                          // 320*66 words
    float* skc = dyn + 320 * SROW;           // 264 words
    __half* tb = (__half*)(skc + 264);       // 8*528 halfs

    int tid = threadIdx.x;
    int ctile = blockIdx.x * 64;
    int wtile = blockIdx.x * 8;
    int ytile = blockIdx.y * 64;

    for (int i = tid; i < 264; i += 256) skc[i] = g_kcp[i];

    {
        int cloc = tid >> 3;
        int uoff = tid & 7;
        const float* src0 = g_Rb + (ctile + cloc) * Hh;
        const float* src1 = g_Rb + (ctile + 32 + cloc) * Hh;
#pragma unroll
        for (int u = uoff; u < 320; u += 8) {
            int y = ytile + u - 128;
            if (y < 0) y += Hh; else if (y >= Hh) y -= Hh;
            s[u * SROW + cloc * 2]     = src0[y];
            s[u * SROW + cloc * 2 + 1] = src1[y];
        }
    }
    __syncthreads();

    int lane = tid & 31;
    int wi = tid >> 5;
    int y0 = wi << 3;

    unsigned long long a64[8] = {0,0,0,0,0,0,0,0};
    unsigned long long k2[8] = {0,0,0,0,0,0,0,0};
    const float* srow = s + y0 * SROW + lane * 2;

#pragma unroll 8
    for (int ss = 0; ss < 264; ss++) {
        unsigned long long d = *(const unsigned long long*)(srow + ss * SROW);
#pragma unroll
        for (int r = 7; r > 0; r--) k2[r] = k2[r - 1];
        {
            unsigned int ki = __float_as_uint(skc[ss]);
            unsigned long long kn;
            asm("mov.b64 %0, {%1, %1};" : "=l"(kn) : "r"(ki));
            k2[0] = kn;
        }
#pragma unroll
        for (int r = 0; r < 8; r++) FMA_F32X2(a64[r], d, k2[r]);
    }

    {
        int w4a = lane >> 3, nn = lane & 7;
        __half* pa = tb + w4a * TBW + y0 * 8 + nn;
        __half* pb = tb + (w4a + 4) * TBW + y0 * 8 + nn;
#pragma unroll
        for (int r = 0; r < 8; r++) {
            float2 f = *(float2*)&a64[r];
            pa[r * 8] = __float2half_rn(f.x);
            pb[r * 8] = __float2half_rn(f.y);
        }
    }
    __syncthreads();

#pragma unroll
    for (int rr = tid; rr < 512; rr += 256) {
        int w4 = rr >> 6, yy = rr & 63;
        uint4 v = *(uint4*)(tb + w4 * TBW + yy * 8);
        *(uint4*)(g_blend2 + ((size_t)(wtile + w4) * Hh + ytile + yy) * 8) = v;
    }
}

// ---------------- stage E: backprojection v3 — L2-traffic-halved ----------------
// grid (8,16)=128 blocks (1 per SM), 512 threads, tile 64j x 32i (2048 px/block).
// 4-angle double-buffered smem staging (96KB dynamic), XOR row swizzle, 1 sync / 4 angles.
__global__ void __launch_bounds__(512, 1) backproj_kernel(float* __restrict__ out) {
    extern __shared__ __align__(16) uint4 ph[];   // 2 bufs x 4 slices x 768 rows = 96KB
    __shared__ float shA[Ww], shB[Ww];

    int tid = threadIdx.x;
    if (tid < Ww) { shA[tid] = g_A[tid]; shB[tid] = g_B[tid]; }

    int warp = tid >> 5, lane = tid & 31;
    int lj = lane & 7, li = lane >> 3;        // warp footprint 8j x 4i
    int jgrp = warp & 7, igrp = warp >> 3;
    int j = blockIdx.x * 64 + jgrp * 8 + lj;
    float jr = (float)(j - 256);
    int i_base = blockIdx.y * 32 + igrp * 16 + li;
    float ir[4];
#pragma unroll
    for (int r = 0; r < 4; r++) ir[r] = (float)(i_base + 4 * r - 256);

    const uint4* g16 = (const uint4*)g_blend2;    // 768 uint4 per angle slice
    uint4 pf[6];
#pragma unroll
    for (int k = 0; k < 6; k++) pf[k] = g16[tid + 512 * k];   // round 0: slices 0..3

    float acc[4][8] = {};

    for (int rnd = 0; rnd < 90; rnd++) {
        uint4* buf = ph + (rnd & 1) * 3072;
        // stage current round's 4 slices (pf holds them), XOR-swizzled rows
#pragma unroll
        for (int k = 0; k < 6; k++) {
            int idx = tid + 512 * k;          // 0..3071
            int s = idx / 768;
            int row = idx - s * 768;
            int rs = row ^ ((row >> 3) & 7);
            buf[s * 768 + rs] = pf[k];
        }
        __syncthreads();
        // prefetch next round (overlaps compute)
        if (rnd + 1 < 90) {
            const uint4* src = g16 + (rnd + 1) * 3072;
#pragma unroll
            for (int k = 0; k < 6; k++) pf[k] = src[tid + 512 * k];
        }

        __half2 pacc[4][4];
#pragma unroll
        for (int r = 0; r < 4; r++)
#pragma unroll
            for (int q = 0; q < 4; q++) pacc[r][q] = __float2half2_rn(0.0f);

        __half2 hones = __float2half2_rn(1.0f);
#pragma unroll
        for (int h = 0; h < 4; h++) {
            int a = 4 * rnd + h;
            float A = shA[a], B = shB[a];
            float base = fmaf(A, jr, 383.5f);
            const uint4* rows = buf + h * 768;
#pragma unroll
            for (int r = 0; r < 4; r++) {
                float py = fmaf(B, ir[r], base);   // in [21.9, 745.1]
                int y0 = (int)py;
                float wy = py - (float)y0;
                __half2 hw1 = __float2half2_rn(wy);
                __half2 hw0 = __hsub2(hones, hw1);
                int y0s = y0 ^ ((y0 >> 3) & 7);
                int y1 = y0 + 1;
                int y1s = y1 ^ ((y1 >> 3) & 7);
                uint4 ra = rows[y0s];
                uint4 rb = rows[y1s];
                const unsigned int* au = (const unsigned int*)&ra;
                const unsigned int* bu = (const unsigned int*)&rb;
#pragma unroll
                for (int q = 0; q < 4; q++) {
                    __half2 va = *(__half2*)&au[q];
                    __half2 vb = *(__half2*)&bu[q];
                    pacc[r][q] = __hfma2(va, hw0, pacc[r][q]);
                    pacc[r][q] = __hfma2(vb, hw1, pacc[r][q]);
                }
            }
        }

        // flush 4-angle half2 partials into fp32 accumulators
#pragma unroll
        for (int r = 0; r < 4; r++)
#pragma unroll
            for (int q = 0; q < 4; q++) {
                float2 f = __half22float2(pacc[r][q]);
                acc[r][2 * q]     += f.x;
                acc[r][2 * q + 1] += f.y;
            }
        __syncthreads();          // all reads of buf done before next round's STS
    }

    const float SC = (float)(PI_D / 720.0);   // pi / (2W)
#pragma unroll
    for (int r = 0; r < 4; r++) {
        int i = i_base + 4 * r;
#pragma unroll
        for (int n = 0; n < 8; n++)
            out[n * (Dd * Dd) + i * Dd + j] = acc[r][n] * SC;
    }
}

// ---------------- launch ----------------
extern "C" void kernel_launch(void* const* d_in, const int* in_sizes, int n_in,
                              void* d_out, int out_size) {
    (void)in_sizes; (void)n_in; (void)out_size;
    const float* radon = (const float*)d_in[0];
    const float* hG    = (const float*)d_in[1];
    float* out = (float*)d_out;

    const int conv_smem = (320 * SROW + 264) * 4 + 8 * TBW * 2;   // 93,984 B
    cudaFuncSetAttribute(conv_kernel, cudaFuncAttributeMaxDynamicSharedMemorySize, conv_smem);
    const int bp_smem = 2 * 4 * Hh * 16;                           // 98,304 B
    cudaFuncSetAttribute(backproj_kernel, cudaFuncAttributeMaxDynamicSharedMemorySize, bp_smem);

    compute_kcp_kernel<<<264, 256>>>(hG);
    params_kernel<<<1, 384>>>();
    rb_kernel<<<dim3(24, 8), 256>>>(radon);
    conv_kernel<<<dim3(45, 12), 256, conv_smem>>>();
    backproj_kernel<<<dim3(8, 16), 512, bp_smem>>>(out);
}

// round 8
// speedup vs baseline: 2.0381x; 1.0750x over previous
#include <cuda_runtime.h>
#include <cuda_fp16.h>

#define Nn 8
#define Hh 768
#define Ww 360
#define Dd 512
#define Cc (Ww*Nn)          // 2880 columns, c = w*8 + n
#define TAPS 257            // band: |d| <= 128
#define PI_D 3.14159265358979323846

// ---------------- scratch (no allocation allowed) ----------------
__device__ float g_kcp[264];                 // kcp[s] = k_signed(s-128), zero-padded to 264
__device__ float g_Rb[Cc*Hh];                // x-blended radon columns, [c][y]
__device__ __align__(16) __half g_blend2[(size_t)Ww*Hh*Nn];  // filtered, [w][y][n] fp16
__device__ float g_A[Ww], g_B[Ww];
__device__ int   g_x0[Ww], g_x1[Ww];
__device__ float g_w0[Ww], g_w1[Ww];

// packed fp32x2 FMA (Blackwell)
#define FMA_F32X2(acc, d, k) asm("fma.rn.f32x2 %0, %1, %2, %0;" : "+l"(acc) : "l"(d), "l"(k))

// ---------------- stage A: banded filter taps via double DFT ----------------
__global__ void compute_kcp_kernel(const float* __restrict__ hG) {
    int m = blockIdx.x;          // 0..263
    int t = threadIdx.x;
    double acc = 0.0;
    if (m < TAPS) {
        double dd = (double)(m - 128);
        double ang = 2.0 * PI_D * dd / (double)Hh;
        for (int u = t; u < Hh; u += 256)
            acc += (double)hG[u] * cos(ang * (double)u);
    }
    __shared__ double red[256];
    red[t] = acc;
    __syncthreads();
    for (int s = 128; s > 0; s >>= 1) {
        if (t < s) red[t] += red[t + s];
        __syncthreads();
    }
    if (t == 0) g_kcp[m] = (m < TAPS) ? (float)(red[0] / (double)Hh) : 0.0f;
}

// ---------------- stage B: per-angle params (replicates reference f32 math) ----------------
__global__ void params_kernel() {
    int w = threadIdx.x;
    if (w >= Ww) return;
    float thf = __double2float_rn(PI_D / 180.0) * (0.5f * (float)w);
    double c = cos((double)thf), s = sin((double)thf);
    double sc = 383.5 / 384.0;
    g_A[w] = (float)(c * sc);
    g_B[w] = (float)(-s * sc);
    float step = __double2float_rn(2.0 / 359.0);
    float tx = -1.0f + (float)w * step;
    float px = (tx + 1.0f) * 179.5f;
    float x0f = floorf(px);
    float wx = px - x0f;
    int ix0 = (int)x0f, ix1 = ix0 + 1;
    float v0 = (ix0 >= 0 && ix0 < Ww) ? 1.0f : 0.0f;
    float v1 = (ix1 >= 0 && ix1 < Ww) ? 1.0f : 0.0f;
    g_w0[w] = (1.0f - wx) * v0;
    g_w1[w] = wx * v1;
    g_x0[w] = min(max(ix0, 0), Ww - 1);
    g_x1[w] = min(max(ix1, 0), Ww - 1);
}

// ---------------- stage C: x-blend, smem-tiled (coalesced in AND out) ----------------
__global__ void __launch_bounds__(256) rb_kernel(const float* __restrict__ radon) {
    __shared__ float sm[32 * 361];     // stride 361: conflict-free
    int n = blockIdx.y;
    int yt = blockIdx.x * 32;
    int tid = threadIdx.x;
    const float* src = radon + ((size_t)n * Hh + yt) * Ww;
#pragma unroll
    for (int idx = tid; idx < 32 * Ww; idx += 256) {
        int y = idx / Ww, x = idx - y * Ww;
        sm[y * 361 + x] = src[y * Ww + x];
    }
    __syncthreads();
#pragma unroll
    for (int idx = tid; idx < Ww * 32; idx += 256) {
        int w = idx >> 5, y = idx & 31;
        float v = sm[y * 361 + g_x0[w]] * g_w0[w] + sm[y * 361 + g_x1[w]] * g_w1[w];
        g_Rb[(size_t)(w * 8 + n) * Hh + yt + y] = v;
    }
}

// ---------------- stage D: 257-tap circular band conv (proven 35.8us) ----------
#define SROW 66                     // words per row (32 float2 + 1 pad float2)
#define TBW 528                     // halfs per w4 slice in transpose buf
__global__ void __launch_bounds__(256) conv_kernel() {
    extern __shared__ float dyn[];
    float* s = dyn;                          // 320*66 words
    float* skc = dyn + 320 * SROW;           // 264 words
    __half* tb = (__half*)(skc + 264);       // 8*528 halfs

    int tid = threadIdx.x;
    int ctile = blockIdx.x * 64;
    int wtile = blockIdx.x * 8;
    int ytile = blockIdx.y * 64;

    for (int i = tid; i < 264; i += 256) skc[i] = g_kcp[i];

    {
        int cloc = tid >> 3;
        int uoff = tid & 7;
        const float* src0 = g_Rb + (ctile + cloc) * Hh;
        const float* src1 = g_Rb + (ctile + 32 + cloc) * Hh;
#pragma unroll
        for (int u = uoff; u < 320; u += 8) {
            int y = ytile + u - 128;
            if (y < 0) y += Hh; else if (y >= Hh) y -= Hh;
            s[u * SROW + cloc * 2]     = src0[y];
            s[u * SROW + cloc * 2 + 1] = src1[y];
        }
    }
    __syncthreads();

    int lane = tid & 31;
    int wi = tid >> 5;
    int y0 = wi << 3;

    unsigned long long a64[8] = {0,0,0,0,0,0,0,0};
    unsigned long long k2[8] = {0,0,0,0,0,0,0,0};
    const float* srow = s + y0 * SROW + lane * 2;

#pragma unroll 8
    for (int ss = 0; ss < 264; ss++) {
        unsigned long long d = *(const unsigned long long*)(srow + ss * SROW);
#pragma unroll
        for (int r = 7; r > 0; r--) k2[r] = k2[r - 1];
        {
            unsigned int ki = __float_as_uint(skc[ss]);
            unsigned long long kn;
            asm("mov.b64 %0, {%1, %1};" : "=l"(kn) : "r"(ki));
            k2[0] = kn;
        }
#pragma unroll
        for (int r = 0; r < 8; r++) FMA_F32X2(a64[r], d, k2[r]);
    }

    {
        int w4a = lane >> 3, nn = lane & 7;
        __half* pa = tb + w4a * TBW + y0 * 8 + nn;
        __half* pb = tb + (w4a + 4) * TBW + y0 * 8 + nn;
#pragma unroll
        for (int r = 0; r < 8; r++) {
            float2 f = *(float2*)&a64[r];
            pa[r * 8] = __float2half_rn(f.x);
            pb[r * 8] = __float2half_rn(f.y);
        }
    }
    __syncthreads();

#pragma unroll
    for (int rr = tid; rr < 512; rr += 256) {
        int w4 = rr >> 6, yy = rr & 63;
        uint4 v = *(uint4*)(tb + w4 * TBW + yy * 8);
        *(uint4*)(g_blend2 + ((size_t)(wtile + w4) * Hh + ytile + yy) * 8) = v;
    }
}

// ---------------- stage E: backprojection v4 — 32 warps/SM for latency hiding ----------------
// grid (8,16)=128 blocks, 1024 threads, tile 64j x 32i; thread: 2 i (stride 16) x 8 batches.
// 4-angle double-buffered smem (96KB), XOR row swizzle, hoisted staging offsets.
__global__ void __launch_bounds__(1024, 1) backproj_kernel(float* __restrict__ out) {
    extern __shared__ __align__(16) uint4 ph[];   // 2 bufs x 4 slices x 768 rows = 96KB
    __shared__ float shA[Ww], shB[Ww];

    int tid = threadIdx.x;
    if (tid < Ww) { shA[tid] = g_A[tid]; shB[tid] = g_B[tid]; }

    int warp = tid >> 5, lane = tid & 31;
    int lj = lane & 7, li = lane >> 3;        // warp footprint 8j x 4i
    int jgrp = warp & 7, igrp = warp >> 3;    // 8 j-groups x 4 i-groups
    int j = blockIdx.x * 64 + jgrp * 8 + lj;
    float jr = (float)(j - 256);
    int i_base = blockIdx.y * 32 + igrp * 4 + li;
    float ir[2];
#pragma unroll
    for (int r = 0; r < 2; r++) ir[r] = (float)(i_base + 16 * r - 256);

    // hoisted staging offsets (swizzled) — constant across rounds
    int soff[3];
#pragma unroll
    for (int k = 0; k < 3; k++) {
        int idx = tid + 1024 * k;             // 0..3071
        int s = idx / 768;
        int row = idx - s * 768;
        int rs = row ^ ((row >> 3) & 7);
        soff[k] = s * 768 + rs;
    }

    const uint4* g16 = (const uint4*)g_blend2;    // 768 uint4 per angle slice
    uint4 pf[3];
#pragma unroll
    for (int k = 0; k < 3; k++) pf[k] = g16[tid + 1024 * k];   // round 0: slices 0..3

    float acc[2][8] = {};
    __half2 hones = __float2half2_rn(1.0f);

    for (int rnd = 0; rnd < 90; rnd++) {
        uint4* buf = ph + (rnd & 1) * 3072;
#pragma unroll
        for (int k = 0; k < 3; k++) buf[soff[k]] = pf[k];
        __syncthreads();
        if (rnd + 1 < 90) {                   // prefetch next round, overlaps compute
            const uint4* src = g16 + (rnd + 1) * 3072;
#pragma unroll
            for (int k = 0; k < 3; k++) pf[k] = src[tid + 1024 * k];
        }

        __half2 pacc[2][4];
#pragma unroll
        for (int r = 0; r < 2; r++)
#pragma unroll
            for (int q = 0; q < 4; q++) pacc[r][q] = __float2half2_rn(0.0f);

#pragma unroll
        for (int h = 0; h < 4; h++) {
            int a = 4 * rnd + h;
            float A = shA[a], B = shB[a];
            float base = fmaf(A, jr, 383.5f);
            const uint4* rows = buf + h * 768;
#pragma unroll
            for (int r = 0; r < 2; r++) {
                float py = fmaf(B, ir[r], base);   // in [21.9, 745.1]
                int y0 = (int)py;
                float wy = py - (float)y0;
                __half2 hw1 = __float2half2_rn(wy);
                __half2 hw0 = __hsub2(hones, hw1);
                int y0s = y0 ^ ((y0 >> 3) & 7);
                int y1 = y0 + 1;
                int y1s = y1 ^ ((y1 >> 3) & 7);
                uint4 ra = rows[y0s];
                uint4 rb = rows[y1s];
                const unsigned int* au = (const unsigned int*)&ra;
                const unsigned int* bu = (const unsigned int*)&rb;
#pragma unroll
                for (int q = 0; q < 4; q++) {
                    __half2 va = *(__half2*)&au[q];
                    __half2 vb = *(__half2*)&bu[q];
                    pacc[r][q] = __hfma2(va, hw0, pacc[r][q]);
                    pacc[r][q] = __hfma2(vb, hw1, pacc[r][q]);
                }
            }
        }

        // flush 4-angle half2 partials into fp32 accumulators
#pragma unroll
        for (int r = 0; r < 2; r++)
#pragma unroll
            for (int q = 0; q < 4; q++) {
                float2 f = __half22float2(pacc[r][q]);
                acc[r][2 * q]     += f.x;
                acc[r][2 * q + 1] += f.y;
            }
        __syncthreads();          // all reads of buf done before next round's STS
    }

    const float SC = (float)(PI_D / 720.0);   // pi / (2W)
#pragma unroll
    for (int r = 0; r < 2; r++) {
        int i = i_base + 16 * r;
#pragma unroll
        for (int n = 0; n < 8; n++)
            out[n * (Dd * Dd) + i * Dd + j] = acc[r][n] * SC;
    }
}

// ---------------- launch ----------------
extern "C" void kernel_launch(void* const* d_in, const int* in_sizes, int n_in,
                              void* d_out, int out_size) {
    (void)in_sizes; (void)n_in; (void)out_size;
    const float* radon = (const float*)d_in[0];
    const float* hG    = (const float*)d_in[1];
    float* out = (float*)d_out;

    const int conv_smem = (320 * SROW + 264) * 4 + 8 * TBW * 2;   // 93,984 B
    cudaFuncSetAttribute(conv_kernel, cudaFuncAttributeMaxDynamicSharedMemorySize, conv_smem);
    const int bp_smem = 2 * 4 * Hh * 16;                           // 98,304 B
    cudaFuncSetAttribute(backproj_kernel, cudaFuncAttributeMaxDynamicSharedMemorySize, bp_smem);

    compute_kcp_kernel<<<264, 256>>>(hG);
    params_kernel<<<1, 384>>>();
    rb_kernel<<<dim3(24, 8), 256>>>(radon);
    conv_kernel<<<dim3(45, 12), 256, conv_smem>>>();
    backproj_kernel<<<dim3(8, 16), 1024, bp_smem>>>(out);
}

// round 9
// speedup vs baseline: 2.3236x; 1.1401x over previous
#include <cuda_runtime.h>
#include <cuda_fp16.h>

#define Nn 8
#define Hh 768
#define Ww 360
#define Dd 512
#define Cc (Ww*Nn)          // 2880 columns, c = w*8 + n
#define TAPS 257            // band: |d| <= 128
#define PI_D 3.14159265358979323846

// ---------------- scratch (no allocation allowed) ----------------
__device__ float g_kcp[264];                 // kcp[s] = k_signed(s-128), zero-padded to 264
__device__ float g_Rb[Cc*Hh];                // x-blended radon columns, [c][y]
__device__ __align__(16) __half g_blend2[(size_t)Ww*Hh*Nn];  // filtered, [w][y][n] fp16
__device__ float g_A[Ww], g_B[Ww];
__device__ int   g_x0[Ww], g_x1[Ww];
__device__ float g_w0[Ww], g_w1[Ww];

// packed fp32x2 FMA (Blackwell)
#define FMA_F32X2(acc, d, k) asm("fma.rn.f32x2 %0, %1, %2, %0;" : "+l"(acc) : "l"(d), "l"(k))

// ---------------- stage A: banded filter taps via double DFT ----------------
__global__ void compute_kcp_kernel(const float* __restrict__ hG) {
    int m = blockIdx.x;          // 0..263
    int t = threadIdx.x;
    double acc = 0.0;
    if (m < TAPS) {
        double dd = (double)(m - 128);
        double ang = 2.0 * PI_D * dd / (double)Hh;
        for (int u = t; u < Hh; u += 256)
            acc += (double)hG[u] * cos(ang * (double)u);
    }
    __shared__ double red[256];
    red[t] = acc;
    __syncthreads();
    for (int s = 128; s > 0; s >>= 1) {
        if (t < s) red[t] += red[t + s];
        __syncthreads();
    }
    if (t == 0) g_kcp[m] = (m < TAPS) ? (float)(red[0] / (double)Hh) : 0.0f;
}

// ---------------- stage B: per-angle params (replicates reference f32 math) ----------------
__global__ void params_kernel() {
    int w = threadIdx.x;
    if (w >= Ww) return;
    float thf = __double2float_rn(PI_D / 180.0) * (0.5f * (float)w);
    double c = cos((double)thf), s = sin((double)thf);
    double sc = 383.5 / 384.0;
    g_A[w] = (float)(c * sc);
    g_B[w] = (float)(-s * sc);
    float step = __double2float_rn(2.0 / 359.0);
    float tx = -1.0f + (float)w * step;
    float px = (tx + 1.0f) * 179.5f;
    float x0f = floorf(px);
    float wx = px - x0f;
    int ix0 = (int)x0f, ix1 = ix0 + 1;
    float v0 = (ix0 >= 0 && ix0 < Ww) ? 1.0f : 0.0f;
    float v1 = (ix1 >= 0 && ix1 < Ww) ? 1.0f : 0.0f;
    g_w0[w] = (1.0f - wx) * v0;
    g_w1[w] = wx * v1;
    g_x0[w] = min(max(ix0, 0), Ww - 1);
    g_x1[w] = min(max(ix1, 0), Ww - 1);
}

// ---------------- stage C: x-blend, smem-tiled (coalesced in AND out) ----------------
__global__ void __launch_bounds__(256) rb_kernel(const float* __restrict__ radon) {
    __shared__ float sm[32 * 361];     // stride 361: conflict-free
    int n = blockIdx.y;
    int yt = blockIdx.x * 32;
    int tid = threadIdx.x;
    const float* src = radon + ((size_t)n * Hh + yt) * Ww;
#pragma unroll
    for (int idx = tid; idx < 32 * Ww; idx += 256) {
        int y = idx / Ww, x = idx - y * Ww;
        sm[y * 361 + x] = src[y * Ww + x];
    }
    __syncthreads();
#pragma unroll
    for (int idx = tid; idx < Ww * 32; idx += 256) {
        int w = idx >> 5, y = idx & 31;
        float v = sm[y * 361 + g_x0[w]] * g_w0[w] + sm[y * 361 + g_x1[w]] * g_w1[w];
        g_Rb[(size_t)(w * 8 + n) * Hh + yt + y] = v;
    }
}

// ---------------- stage D: 257-tap circular band conv (proven 35.8us) ----------
#define SROW 66                     // words per row (32 float2 + 1 pad float2)
#define TBW 528                     // halfs per w4 slice in transpose buf
__global__ void __launch_bounds__(256) conv_kernel() {
    extern __shared__ float dyn[];
    float* s = dyn;                          // 320*66 words
    float* skc = dyn + 320 * SROW;           // 264 words
    __half* tb = (__half*)(skc + 264);       // 8*528 halfs

    int tid = threadIdx.x;
    int ctile = blockIdx.x * 64;
    int wtile = blockIdx.x * 8;
    int ytile = blockIdx.y * 64;

    for (int i = tid; i < 264; i += 256) skc[i] = g_kcp[i];

    {
        int cloc = tid >> 3;
        int uoff = tid & 7;
        const float* src0 = g_Rb + (ctile + cloc) * Hh;
        const float* src1 = g_Rb + (ctile + 32 + cloc) * Hh;
#pragma unroll
        for (int u = uoff; u < 320; u += 8) {
            int y = ytile + u - 128;
            if (y < 0) y += Hh; else if (y >= Hh) y -= Hh;
            s[u * SROW + cloc * 2]     = src0[y];
            s[u * SROW + cloc * 2 + 1] = src1[y];
        }
    }
    __syncthreads();

    int lane = tid & 31;
    int wi = tid >> 5;
    int y0 = wi << 3;

    unsigned long long a64[8] = {0,0,0,0,0,0,0,0};
    unsigned long long k2[8] = {0,0,0,0,0,0,0,0};
    const float* srow = s + y0 * SROW + lane * 2;

#pragma unroll 8
    for (int ss = 0; ss < 264; ss++) {
        unsigned long long d = *(const unsigned long long*)(srow + ss * SROW);
#pragma unroll
        for (int r = 7; r > 0; r--) k2[r] = k2[r - 1];
        {
            unsigned int ki = __float_as_uint(skc[ss]);
            unsigned long long kn;
            asm("mov.b64 %0, {%1, %1};" : "=l"(kn) : "r"(ki));
            k2[0] = kn;
        }
#pragma unroll
        for (int r = 0; r < 8; r++) FMA_F32X2(a64[r], d, k2[r]);
    }

    {
        int w4a = lane >> 3, nn = lane & 7;
        __half* pa = tb + w4a * TBW + y0 * 8 + nn;
        __half* pb = tb + (w4a + 4) * TBW + y0 * 8 + nn;
#pragma unroll
        for (int r = 0; r < 8; r++) {
            float2 f = *(float2*)&a64[r];
            pa[r * 8] = __float2half_rn(f.x);
            pb[r * 8] = __float2half_rn(f.y);
        }
    }
    __syncthreads();

#pragma unroll
    for (int rr = tid; rr < 512; rr += 256) {
        int w4 = rr >> 6, yy = rr & 63;
        uint4 v = *(uint4*)(tb + w4 * TBW + yy * 8);
        *(uint4*)(g_blend2 + ((size_t)(wtile + w4) * Hh + ytile + yy) * 8) = v;
    }
}

// ---------------- stage E: backprojection v5 — TMA bulk 3-stage pipeline ----------------
// grid (8,16)=128 blocks, 1024 threads, tile 64j x 32i; thread: 2 i (stride 16) x 8 batches.
// 3 stages x 4 angles x 48KB staged by cp.async.bulk; mbarrier completion; 1 sync/round.
#define BP_STAGES 3
#define BP_ANG 4
#define BP_STAGE_U4 (BP_ANG * Hh)              // 3072 uint4 per stage
#define BP_STAGE_BYTES (BP_STAGE_U4 * 16)      // 49152 B
__global__ void __launch_bounds__(1024, 1) backproj_kernel(float* __restrict__ out) {
    extern __shared__ __align__(16) uint4 ph[];   // 3 stages x 3072 uint4 = 144KB
    __shared__ float shA[Ww], shB[Ww];
    __shared__ __align__(8) unsigned long long mbar[BP_STAGES];

    int tid = threadIdx.x;
    if (tid < Ww) { shA[tid] = g_A[tid]; shB[tid] = g_B[tid]; }

    unsigned int mbar_base;
    {
        unsigned long long gp = (unsigned long long)mbar;
        asm("{ .reg .u64 t; cvta.to.shared.u64 t, %1; cvt.u32.u64 %0, t; }"
            : "=r"(mbar_base) : "l"(gp));
    }
    unsigned int ph_base;
    {
        unsigned long long gp = (unsigned long long)ph;
        asm("{ .reg .u64 t; cvta.to.shared.u64 t, %1; cvt.u32.u64 %0, t; }"
            : "=r"(ph_base) : "l"(gp));
    }

    if (tid < BP_STAGES)
        asm volatile("mbarrier.init.shared.b64 [%0], %1;"
                     :: "r"(mbar_base + tid * 8), "r"(1) : "memory");
    __syncthreads();

    const char* gsrc = (const char*)g_blend2;
    if (tid == 0) {
#pragma unroll
        for (int s = 0; s < BP_STAGES; s++) {
            unsigned int mb = mbar_base + s * 8;
            asm volatile("mbarrier.arrive.expect_tx.shared.b64 _, [%0], %1;"
                         :: "r"(mb), "r"(BP_STAGE_BYTES) : "memory");
            asm volatile("cp.async.bulk.shared::cta.global.mbarrier::complete_tx::bytes "
                         "[%0], [%1], %2, [%3];"
                         :: "r"(ph_base + s * BP_STAGE_BYTES),
                            "l"(gsrc + (size_t)s * BP_STAGE_BYTES),
                            "r"(BP_STAGE_BYTES), "r"(mb) : "memory");
        }
    }

    int warp = tid >> 5, lane = tid & 31;
    int lj = lane & 7, li = lane >> 3;        // warp footprint 8j x 4i
    int jgrp = warp & 7, igrp = warp >> 3;
    int j = blockIdx.x * 64 + jgrp * 8 + lj;
    float jr = (float)(j - 256);
    int i_base = blockIdx.y * 32 + igrp * 4 + li;
    float ir[2];
#pragma unroll
    for (int r = 0; r < 2; r++) ir[r] = (float)(i_base + 16 * r - 256);

    float acc[2][8] = {};
    __half2 hones = __float2half2_rn(1.0f);

    for (int rnd = 0; rnd < 90; rnd++) {
        int b = rnd % BP_STAGES;
        unsigned int mb = mbar_base + b * 8;
        unsigned int parity = (unsigned int)((rnd / BP_STAGES) & 1);
        // wait for this stage's bulk copy
        {
            unsigned int done;
            asm volatile(
                "{\n\t.reg .pred p;\n\t"
                "mbarrier.try_wait.parity.shared.b64 p, [%1], %2;\n\t"
                "selp.b32 %0, 1, 0, p;\n\t}"
                : "=r"(done) : "r"(mb), "r"(parity) : "memory");
            while (!done) {
                asm volatile(
                    "{\n\t.reg .pred p;\n\t"
                    "mbarrier.try_wait.parity.shared.b64 p, [%1], %2, 0x989680;\n\t"
                    "selp.b32 %0, 1, 0, p;\n\t}"
                    : "=r"(done) : "r"(mb), "r"(parity) : "memory");
            }
        }

        const uint4* buf = ph + b * BP_STAGE_U4;

        __half2 pacc[2][4];
#pragma unroll
        for (int r = 0; r < 2; r++)
#pragma unroll
            for (int q = 0; q < 4; q++) pacc[r][q] = __float2half2_rn(0.0f);

#pragma unroll
        for (int h = 0; h < BP_ANG; h++) {
            int a = BP_ANG * rnd + h;
            float A = shA[a], B = shB[a];
            float base = fmaf(A, jr, 383.5f);
            const uint4* rows = buf + h * Hh;
#pragma unroll
            for (int r = 0; r < 2; r++) {
                float py = fmaf(B, ir[r], base);   // in [21.9, 745.1]
                int y0 = (int)py;
                float wy = py - (float)y0;
                __half2 hw1 = __float2half2_rn(wy);
                __half2 hw0 = __hsub2(hones, hw1);
                uint4 ra = rows[y0];               // rows y mod 8 distinct in warp: conflict-free
                uint4 rb = rows[y0 + 1];
                const unsigned int* au = (const unsigned int*)&ra;
                const unsigned int* bu = (const unsigned int*)&rb;
#pragma unroll
                for (int q = 0; q < 4; q++) {
                    __half2 va = *(__half2*)&au[q];
                    __half2 vb = *(__half2*)&bu[q];
                    pacc[r][q] = __hfma2(va, hw0, pacc[r][q]);
                    pacc[r][q] = __hfma2(vb, hw1, pacc[r][q]);
                }
            }
        }

        // flush 4-angle half2 partials into fp32 accumulators
#pragma unroll
        for (int r = 0; r < 2; r++)
#pragma unroll
            for (int q = 0; q < 4; q++) {
                float2 f = __half22float2(pacc[r][q]);
                acc[r][2 * q]     += f.x;
                acc[r][2 * q + 1] += f.y;
            }

        __syncthreads();            // all readers of stage b done
        if (tid == 0 && rnd + BP_STAGES < 90) {
            asm volatile("mbarrier.arrive.expect_tx.shared.b64 _, [%0], %1;"
                         :: "r"(mb), "r"(BP_STAGE_BYTES) : "memory");
            asm volatile("cp.async.bulk.shared::cta.global.mbarrier::complete_tx::bytes "
                         "[%0], [%1], %2, [%3];"
                         :: "r"(ph_base + b * BP_STAGE_BYTES),
                            "l"(gsrc + (size_t)(rnd + BP_STAGES) * BP_STAGE_BYTES),
                            "r"(BP_STAGE_BYTES), "r"(mb) : "memory");
        }
    }

    const float SC = (float)(PI_D / 720.0);   // pi / (2W)
#pragma unroll
    for (int r = 0; r < 2; r++) {
        int i = i_base + 16 * r;
#pragma unroll
        for (int n = 0; n < 8; n++)
            out[n * (Dd * Dd) + i * Dd + j] = acc[r][n] * SC;
    }
}

// ---------------- launch ----------------
extern "C" void kernel_launch(void* const* d_in, const int* in_sizes, int n_in,
                              void* d_out, int out_size) {
    (void)in_sizes; (void)n_in; (void)out_size;
    const float* radon = (const float*)d_in[0];
    const float* hG    = (const float*)d_in[1];
    float* out = (float*)d_out;

    const int conv_smem = (320 * SROW + 264) * 4 + 8 * TBW * 2;   // 93,984 B
    cudaFuncSetAttribute(conv_kernel, cudaFuncAttributeMaxDynamicSharedMemorySize, conv_smem);
    const int bp_smem = BP_STAGES * BP_STAGE_BYTES;                // 147,456 B
    cudaFuncSetAttribute(backproj_kernel, cudaFuncAttributeMaxDynamicSharedMemorySize, bp_smem);

    compute_kcp_kernel<<<264, 256>>>(hG);
    params_kernel<<<1, 384>>>();
    rb_kernel<<<dim3(24, 8), 256>>>(radon);
    conv_kernel<<<dim3(45, 12), 256, conv_smem>>>();
    backproj_kernel<<<dim3(8, 16), 1024, bp_smem>>>(out);
}

// round 10
// speedup vs baseline: 2.3322x; 1.0037x over previous
#include <cuda_runtime.h>
#include <cuda_fp16.h>

#define Nn 8
#define Hh 768
#define Ww 360
#define Dd 512
#define Cc (Ww*Nn)          // 2880 columns, c = w*8 + n
#define TAPS 257            // band: |d| <= 128
#define TAPP 272            // taps padded to multiple of 16
#define PI_D 3.14159265358979323846
typedef unsigned long long ull;

// ---------------- scratch (no allocation allowed) ----------------
__device__ float g_kcp[TAPP];                // kcp[s] = k_signed(s-128), zero-padded
__device__ float g_Rb[Cc*Hh];                // x-blended radon columns, [c][y]
__device__ __align__(16) __half g_blend2[(size_t)Ww*Hh*Nn];  // filtered, [w][y][n] fp16
__device__ float g_A[Ww], g_B[Ww];
__device__ int   g_x0[Ww], g_x1[Ww];
__device__ float g_w0[Ww], g_w1[Ww];

// packed fp32x2 FMA (Blackwell)
#define FMA_F32X2(acc, d, k) asm("fma.rn.f32x2 %0, %1, %2, %0;" : "+l"(acc) : "l"(d), "l"(k))

// ---------------- stage A: banded filter taps via double DFT ----------------
__global__ void compute_kcp_kernel(const float* __restrict__ hG) {
    int m = blockIdx.x;          // 0..271
    int t = threadIdx.x;
    double acc = 0.0;
    if (m < TAPS) {
        double dd = (double)(m - 128);
        double ang = 2.0 * PI_D * dd / (double)Hh;
        for (int u = t; u < Hh; u += 256)
            acc += (double)hG[u] * cos(ang * (double)u);
    }
    __shared__ double red[256];
    red[t] = acc;
    __syncthreads();
    for (int s = 128; s > 0; s >>= 1) {
        if (t < s) red[t] += red[t + s];
        __syncthreads();
    }
    if (t == 0) g_kcp[m] = (m < TAPS) ? (float)(red[0] / (double)Hh) : 0.0f;
}

// ---------------- stage B: per-angle params (replicates reference f32 math) ----------------
__global__ void params_kernel() {
    int w = threadIdx.x;
    if (w >= Ww) return;
    float thf = __double2float_rn(PI_D / 180.0) * (0.5f * (float)w);
    double c = cos((double)thf), s = sin((double)thf);
    double sc = 383.5 / 384.0;
    g_A[w] = (float)(c * sc);
    g_B[w] = (float)(-s * sc);
    float step = __double2float_rn(2.0 / 359.0);
    float tx = -1.0f + (float)w * step;
    float px = (tx + 1.0f) * 179.5f;
    float x0f = floorf(px);
    float wx = px - x0f;
    int ix0 = (int)x0f, ix1 = ix0 + 1;
    float v0 = (ix0 >= 0 && ix0 < Ww) ? 1.0f : 0.0f;
    float v1 = (ix1 >= 0 && ix1 < Ww) ? 1.0f : 0.0f;
    g_w0[w] = (1.0f - wx) * v0;
    g_w1[w] = wx * v1;
    g_x0[w] = min(max(ix0, 0), Ww - 1);
    g_x1[w] = min(max(ix1, 0), Ww - 1);
}

// ---------------- stage C: x-blend, smem-tiled (coalesced in AND out) ----------------
__global__ void __launch_bounds__(256) rb_kernel(const float* __restrict__ radon) {
    __shared__ float sm[32 * 361];     // stride 361: conflict-free
    int n = blockIdx.y;
    int yt = blockIdx.x * 32;
    int tid = threadIdx.x;
    const float* src = radon + ((size_t)n * Hh + yt) * Ww;
#pragma unroll
    for (int idx = tid; idx < 32 * Ww; idx += 256) {
        int y = idx / Ww, x = idx - y * Ww;
        sm[y * 361 + x] = src[y * Ww + x];
    }
    __syncthreads();
#pragma unroll
    for (int idx = tid; idx < Ww * 32; idx += 256) {
        int w = idx >> 5, y = idx & 31;
        float v = sm[y * 361 + g_x0[w]] * g_w0[w] + sm[y * 361 + g_x1[w]] * g_w1[w];
        g_Rb[(size_t)(w * 8 + n) * Hh + yt + y] = v;
    }
}

// ---------------- stage D: 272-tap band conv, 16 acc/thread, f32x2, out [w][y][n] fp16 ----
// block: 128 thr = 4 warps; tile 64 cols x 64 y; warp = 16 consecutive y; lane = col-pair
#define SROW 66                     // words per row (32 float2 + 1 pad float2)
#define TBW 528                     // halfs per w4 slice in transpose buf
__global__ void __launch_bounds__(128, 2) conv_kernel() {
    extern __shared__ float dyn[];
    float* s = dyn;                                  // 320*66 words = 84480 B
    ull* skc2 = (ull*)(dyn + 320 * SROW);            // 272 duplicated tap pairs = 2176 B
    __half* tb = (__half*)(dyn + 320 * SROW + 544);  // 8*528 halfs = 8448 B

    int tid = threadIdx.x;
    int ctile = blockIdx.x * 64;
    int wtile = blockIdx.x * 8;
    int ytile = blockIdx.y * 64;

    for (int i = tid; i < TAPP; i += 128) {
        unsigned int ki = __float_as_uint(g_kcp[i]);
        ull kn;
        asm("mov.b64 %0, {%1, %1};" : "=l"(kn) : "r"(ki));
        skc2[i] = kn;
    }

    {   // load window (circular wrap): 320 rows x 32 col-pairs
        int cloc = tid >> 2;
        int uoff = tid & 3;
        const float* src0 = g_Rb + (ctile + cloc) * Hh;
        const float* src1 = g_Rb + (ctile + 32 + cloc) * Hh;
#pragma unroll 4
        for (int u = uoff; u < 320; u += 4) {
            int y = ytile + u - 128;
            if (y < 0) y += Hh; else if (y >= Hh) y -= Hh;
            s[u * SROW + cloc * 2]     = src0[y];
            s[u * SROW + cloc * 2 + 1] = src1[y];
        }
    }
    __syncthreads();

    int lane = tid & 31;
    int wi = tid >> 5;
    int y0 = wi << 4;              // 16 y per thread

    ull a64[16] = {};
    ull k2[16] = {};
    const float* srow = s + y0 * SROW + lane * 2;

#pragma unroll 16
    for (int ss = 0; ss < TAPP; ss++) {
        ull d = *(const ull*)(srow + ss * SROW);
#pragma unroll
        for (int r = 15; r > 0; r--) k2[r] = k2[r - 1];
        k2[0] = skc2[ss];
#pragma unroll
        for (int r = 0; r < 16; r++) FMA_F32X2(a64[r], d, k2[r]);
    }

    {   // transpose to [w4][y][n] halfs in smem
        int w4a = lane >> 3, nn = lane & 7;
        __half* pa = tb + w4a * TBW + y0 * 8 + nn;
        __half* pb = tb + (w4a + 4) * TBW + y0 * 8 + nn;
#pragma unroll
        for (int r = 0; r < 16; r++) {
            float2 f = *(float2*)&a64[r];
            pa[r * 8] = __float2half_rn(f.x);
            pb[r * 8] = __float2half_rn(f.y);
        }
    }
    __syncthreads();

#pragma unroll
    for (int rr = tid; rr < 512; rr += 128) {
        int w4 = rr >> 6, yy = rr & 63;
        uint4 v = *(uint4*)(tb + w4 * TBW + yy * 8);
        *(uint4*)(g_blend2 + ((size_t)(wtile + w4) * Hh + ytile + yy) * 8) = v;
    }
}

// ---------------- stage E: backprojection — TMA bulk 4-stage pipeline ----------------
// grid (8,16)=128 blocks, 1024 threads, tile 64j x 32i; thread: 2 i (stride 16) x 8 batches.
#define BP_STAGES 4
#define BP_ANG 4
#define BP_STAGE_U4 (BP_ANG * Hh)              // 3072 uint4 per stage
#define BP_STAGE_BYTES (BP_STAGE_U4 * 16)      // 49152 B
__global__ void __launch_bounds__(1024, 1) backproj_kernel(float* __restrict__ out) {
    extern __shared__ __align__(16) uint4 ph[];   // 4 stages x 3072 uint4 = 192KB
    __shared__ float shA[Ww], shB[Ww];
    __shared__ __align__(8) unsigned long long mbar[BP_STAGES];

    int tid = threadIdx.x;
    if (tid < Ww) { shA[tid] = g_A[tid]; shB[tid] = g_B[tid]; }

    unsigned int mbar_base;
    {
        unsigned long long gp = (unsigned long long)mbar;
        asm("{ .reg .u64 t; cvta.to.shared.u64 t, %1; cvt.u32.u64 %0, t; }"
            : "=r"(mbar_base) : "l"(gp));
    }
    unsigned int ph_base;
    {
        unsigned long long gp = (unsigned long long)ph;
        asm("{ .reg .u64 t; cvta.to.shared.u64 t, %1; cvt.u32.u64 %0, t; }"
            : "=r"(ph_base) : "l"(gp));
    }

    if (tid < BP_STAGES)
        asm volatile("mbarrier.init.shared.b64 [%0], %1;"
                     :: "r"(mbar_base + tid * 8), "r"(1) : "memory");
    __syncthreads();

    const char* gsrc = (const char*)g_blend2;
    if (tid == 0) {
#pragma unroll
        for (int s = 0; s < BP_STAGES; s++) {
            unsigned int mb = mbar_base + s * 8;
            asm volatile("mbarrier.arrive.expect_tx.shared.b64 _, [%0], %1;"
                         :: "r"(mb), "r"(BP_STAGE_BYTES) : "memory");
            asm volatile("cp.async.bulk.shared::cta.global.mbarrier::complete_tx::bytes "
                         "[%0], [%1], %2, [%3];"
                         :: "r"(ph_base + s * BP_STAGE_BYTES),
                            "l"(gsrc + (size_t)s * BP_STAGE_BYTES),
                            "r"(BP_STAGE_BYTES), "r"(mb) : "memory");
        }
    }

    int warp = tid >> 5, lane = tid & 31;
    int lj = lane & 7, li = lane >> 3;        // warp footprint 8j x 4i
    int jgrp = warp & 7, igrp = warp >> 3;
    int j = blockIdx.x * 64 + jgrp * 8 + lj;
    float jr = (float)(j - 256);
    int i_base = blockIdx.y * 32 + igrp * 4 + li;
    float ir[2];
#pragma unroll
    for (int r = 0; r < 2; r++) ir[r] = (float)(i_base + 16 * r - 256);

    float acc[2][8] = {};
    __half2 hones = __float2half2_rn(1.0f);

    for (int rnd = 0; rnd < 90; rnd++) {
        int b = rnd % BP_STAGES;
        unsigned int mb = mbar_base + b * 8;
        unsigned int parity = (unsigned int)((rnd / BP_STAGES) & 1);
        {
            unsigned int done;
            asm volatile(
                "{\n\t.reg .pred p;\n\t"
                "mbarrier.try_wait.parity.shared.b64 p, [%1], %2;\n\t"
                "selp.b32 %0, 1, 0, p;\n\t}"
                : "=r"(done) : "r"(mb), "r"(parity) : "memory");
            while (!done) {
                asm volatile(
                    "{\n\t.reg .pred p;\n\t"
                    "mbarrier.try_wait.parity.shared.b64 p, [%1], %2, 0x989680;\n\t"
                    "selp.b32 %0, 1, 0, p;\n\t}"
                    : "=r"(done) : "r"(mb), "r"(parity) : "memory");
            }
        }

        const uint4* buf = ph + b * BP_STAGE_U4;

        __half2 pacc[2][4];
#pragma unroll
        for (int r = 0; r < 2; r++)
#pragma unroll
            for (int q = 0; q < 4; q++) pacc[r][q] = __float2half2_rn(0.0f);

#pragma unroll
        for (int h = 0; h < BP_ANG; h++) {
            int a = BP_ANG * rnd + h;
            float A = shA[a], B = shB[a];
            float base = fmaf(A, jr, 383.5f);
            const uint4* rows = buf + h * Hh;
#pragma unroll
            for (int r = 0; r < 2; r++) {
                float py = fmaf(B, ir[r], base);   // in [21.9, 745.1]
                int y0 = (int)py;
                float wy = py - (float)y0;
                __half2 hw1 = __float2half2_rn(wy);
                __half2 hw0 = __hsub2(hones, hw1);
                uint4 ra = rows[y0];               // warp y-span < 8: conflict-free
                uint4 rb = rows[y0 + 1];
                const unsigned int* au = (const unsigned int*)&ra;
                const unsigned int* bu = (const unsigned int*)&rb;
#pragma unroll
                for (int q = 0; q < 4; q++) {
                    __half2 va = *(__half2*)&au[q];
                    __half2 vb = *(__half2*)&bu[q];
                    pacc[r][q] = __hfma2(va, hw0, pacc[r][q]);
                    pacc[r][q] = __hfma2(vb, hw1, pacc[r][q]);
                }
            }
        }

#pragma unroll
        for (int r = 0; r < 2; r++)
#pragma unroll
            for (int q = 0; q < 4; q++) {
                float2 f = __half22float2(pacc[r][q]);
                acc[r][2 * q]     += f.x;
                acc[r][2 * q + 1] += f.y;
            }

        __syncthreads();            // all readers of stage b done
        if (tid == 0 && rnd + BP_STAGES < 90) {
            asm volatile("mbarrier.arrive.expect_tx.shared.b64 _, [%0], %1;"
                         :: "r"(mb), "r"(BP_STAGE_BYTES) : "memory");
            asm volatile("cp.async.bulk.shared::cta.global.mbarrier::complete_tx::bytes "
                         "[%0], [%1], %2, [%3];"
                         :: "r"(ph_base + b * BP_STAGE_BYTES),
                            "l"(gsrc + (size_t)(rnd + BP_STAGES) * BP_STAGE_BYTES),
                            "r"(BP_STAGE_BYTES), "r"(mb) : "memory");
        }
    }

    const float SC = (float)(PI_D / 720.0);   // pi / (2W)
#pragma unroll
    for (int r = 0; r < 2; r++) {
        int i = i_base + 16 * r;
#pragma unroll
        for (int n = 0; n < 8; n++)
            out[n * (Dd * Dd) + i * Dd + j] = acc[r][n] * SC;
    }
}

// ---------------- launch ----------------
extern "C" void kernel_launch(void* const* d_in, const int* in_sizes, int n_in,
                              void* d_out, int out_size) {
    (void)in_sizes; (void)n_in; (void)out_size;
    const float* radon = (const float*)d_in[0];
    const float* hG    = (const float*)d_in[1];
    float* out = (float*)d_out;

    const int conv_smem = 320 * SROW * 4 + TAPP * 8 + 8 * TBW * 2;   // 95,104 B
    cudaFuncSetAttribute(conv_kernel, cudaFuncAttributeMaxDynamicSharedMemorySize, conv_smem);
    const int bp_smem = BP_STAGES * BP_STAGE_BYTES;                   // 196,608 B
    cudaFuncSetAttribute(backproj_kernel, cudaFuncAttributeMaxDynamicSharedMemorySize, bp_smem);

    compute_kcp_kernel<<<TAPP, 256>>>(hG);
    params_kernel<<<1, 384>>>();
    rb_kernel<<<dim3(24, 8), 256>>>(radon);
    conv_kernel<<<dim3(45, 12), 128, conv_smem>>>();
    backproj_kernel<<<dim3(8, 16), 1024, bp_smem>>>(out);
}

// round 11
// speedup vs baseline: 2.4531x; 1.0518x over previous
#include <cuda_runtime.h>
#include <cuda_fp16.h>

#define Nn 8
#define Hh 768
#define Ww 360
#define Dd 512
#define Cc (Ww*Nn)          // 2880 columns, c = w*8 + n
#define TAPS 257            // band: |d| <= 128
#define TAPP 272
#define PI_D 3.14159265358979323846
typedef unsigned long long ull;

// ---------------- scratch (no allocation allowed) ----------------
__device__ float g_kcp[TAPP];                // kcp[s] = k_signed(s-128), zero-padded
__device__ float g_Rb[Cc*Hh];                // x-blended radon columns, [c][y]
__device__ __align__(16) __half g_blend2[(size_t)Ww*Hh*Nn];  // filtered, [w][y][n] fp16
__device__ float g_A[Ww], g_B[Ww];
__device__ int   g_x0[Ww], g_x1[Ww];
__device__ float g_w0[Ww], g_w1[Ww];

// packed fp32x2 FMA (Blackwell)
#define FMA_F32X2(acc, d, k) asm("fma.rn.f32x2 %0, %1, %2, %0;" : "+l"(acc) : "l"(d), "l"(k))

// ---------------- stage A: banded filter taps via double DFT ----------------
__global__ void compute_kcp_kernel(const float* __restrict__ hG) {
    int m = blockIdx.x;          // 0..271
    int t = threadIdx.x;
    double acc = 0.0;
    if (m < TAPS) {
        double dd = (double)(m - 128);
        double ang = 2.0 * PI_D * dd / (double)Hh;
        for (int u = t; u < Hh; u += 256)
            acc += (double)hG[u] * cos(ang * (double)u);
    }
    __shared__ double red[256];
    red[t] = acc;
    __syncthreads();
    for (int s = 128; s > 0; s >>= 1) {
        if (t < s) red[t] += red[t + s];
        __syncthreads();
    }
    if (t == 0) g_kcp[m] = (m < TAPS) ? (float)(red[0] / (double)Hh) : 0.0f;
}

// ---------------- stage B: per-angle params (replicates reference f32 math) ----------------
__global__ void params_kernel() {
    int w = threadIdx.x;
    if (w >= Ww) return;
    float thf = __double2float_rn(PI_D / 180.0) * (0.5f * (float)w);
    double c = cos((double)thf), s = sin((double)thf);
    double sc = 383.5 / 384.0;
    g_A[w] = (float)(c * sc);
    g_B[w] = (float)(-s * sc);
    float step = __double2float_rn(2.0 / 359.0);
    float tx = -1.0f + (float)w * step;
    float px = (tx + 1.0f) * 179.5f;
    float x0f = floorf(px);
    float wx = px - x0f;
    int ix0 = (int)x0f, ix1 = ix0 + 1;
    float v0 = (ix0 >= 0 && ix0 < Ww) ? 1.0f : 0.0f;
    float v1 = (ix1 >= 0 && ix1 < Ww) ? 1.0f : 0.0f;
    g_w0[w] = (1.0f - wx) * v0;
    g_w1[w] = wx * v1;
    g_x0[w] = min(max(ix0, 0), Ww - 1);
    g_x1[w] = min(max(ix1, 0), Ww - 1);
}

// ---------------- stage C: x-blend, smem-tiled (coalesced in AND out) ----------------
__global__ void __launch_bounds__(256) rb_kernel(const float* __restrict__ radon) {
    __shared__ float sm[32 * 361];     // stride 361: conflict-free
    int n = blockIdx.y;
    int yt = blockIdx.x * 32;
    int tid = threadIdx.x;
    const float* src = radon + ((size_t)n * Hh + yt) * Ww;
#pragma unroll
    for (int idx = tid; idx < 32 * Ww; idx += 256) {
        int y = idx / Ww, x = idx - y * Ww;
        sm[y * 361 + x] = src[y * Ww + x];
    }
    __syncthreads();
#pragma unroll
    for (int idx = tid; idx < Ww * 32; idx += 256) {
        int w = idx >> 5, y = idx & 31;
        float v = sm[y * 361 + g_x0[w]] * g_w0[w] + sm[y * 361 + g_x1[w]] * g_w1[w];
        g_Rb[(size_t)(w * 8 + n) * Hh + yt + y] = v;
    }
}

// ---------------- stage D: 257-tap circular band conv (proven 35.8us, R4 version) ----------
#define SROW 66                     // words per row (32 float2 + 1 pad float2)
#define TBW 528                     // halfs per w4 slice in transpose buf
__global__ void __launch_bounds__(256) conv_kernel() {
    extern __shared__ float dyn[];
    float* s = dyn;                          // 320*66 words
    float* skc = dyn + 320 * SROW;           // 264 words
    __half* tb = (__half*)(skc + 264);       // 8*528 halfs

    int tid = threadIdx.x;
    int ctile = blockIdx.x * 64;
    int wtile = blockIdx.x * 8;
    int ytile = blockIdx.y * 64;

    for (int i = tid; i < 264; i += 256) skc[i] = g_kcp[i];

    {
        int cloc = tid >> 3;
        int uoff = tid & 7;
        const float* src0 = g_Rb + (ctile + cloc) * Hh;
        const float* src1 = g_Rb + (ctile + 32 + cloc) * Hh;
#pragma unroll
        for (int u = uoff; u < 320; u += 8) {
            int y = ytile + u - 128;
            if (y < 0) y += Hh; else if (y >= Hh) y -= Hh;
            s[u * SROW + cloc * 2]     = src0[y];
            s[u * SROW + cloc * 2 + 1] = src1[y];
        }
    }
    __syncthreads();

    int lane = tid & 31;
    int wi = tid >> 5;
    int y0 = wi << 3;

    ull a64[8] = {0,0,0,0,0,0,0,0};
    ull k2[8] = {0,0,0,0,0,0,0,0};
    const float* srow = s + y0 * SROW + lane * 2;

#pragma unroll 8
    for (int ss = 0; ss < 264; ss++) {
        ull d = *(const ull*)(srow + ss * SROW);
#pragma unroll
        for (int r = 7; r > 0; r--) k2[r] = k2[r - 1];
        {
            unsigned int ki = __float_as_uint(skc[ss]);
            ull kn;
            asm("mov.b64 %0, {%1, %1};" : "=l"(kn) : "r"(ki));
            k2[0] = kn;
        }
#pragma unroll
        for (int r = 0; r < 8; r++) FMA_F32X2(a64[r], d, k2[r]);
    }

    {
        int w4a = lane >> 3, nn = lane & 7;
        __half* pa = tb + w4a * TBW + y0 * 8 + nn;
        __half* pb = tb + (w4a + 4) * TBW + y0 * 8 + nn;
#pragma unroll
        for (int r = 0; r < 8; r++) {
            float2 f = *(float2*)&a64[r];
            pa[r * 8] = __float2half_rn(f.x);
            pb[r * 8] = __float2half_rn(f.y);
        }
    }
    __syncthreads();

#pragma unroll
    for (int rr = tid; rr < 512; rr += 256) {
        int w4 = rr >> 6, yy = rr & 63;
        uint4 v = *(uint4*)(tb + w4 * TBW + yy * 8);
        *(uint4*)(g_blend2 + ((size_t)(wtile + w4) * Hh + ytile + yy) * 8) = v;
    }
}

// ---------------- stage E: backprojection v6 — windowed TMA staging ----------------
// grid (8,16)=128 blocks, 1024 threads, tile 64j x 32i; thread: 2 i (stride 16) x 8 batches.
// Per (block, angle) only an 80-row py-window is staged (1280B) instead of the full 768-row
// slice (12KB): 12x less L2/TMA traffic. 8 angles/stage x 8 stages (80KB smem), mbarrier pipe.
#define BP_STAGES 8
#define BP_ANG 8
#define BP_ROWS 80
#define BP_ANG_BYTES (BP_ROWS * 16)                 // 1280
#define BP_STAGE_U4 (BP_ANG * BP_ROWS)              // 640 uint4
#define BP_STAGE_BYTES (BP_STAGE_U4 * 16)           // 10240
#define BP_ROUNDS (Ww / BP_ANG)                     // 45
__global__ void __launch_bounds__(1024, 1) backproj_kernel(float* __restrict__ out) {
    extern __shared__ __align__(16) uint4 ph[];     // 8 stages x 640 uint4 = 80KB
    __shared__ float shA[Ww], shB[Ww];
    __shared__ int shY[Ww];
    __shared__ __align__(8) unsigned long long mbar[BP_STAGES];

    int tid = threadIdx.x;

    float jr0 = (float)((int)blockIdx.x * 64 - 256);
    float jr1 = jr0 + 63.0f;
    float ir0f = (float)((int)blockIdx.y * 32 - 256);
    float ir1f = ir0f + 31.0f;

    if (tid < Ww) {
        float A = g_A[tid], B = g_B[tid];
        shA[tid] = A; shB[tid] = B;
        float minpy = fminf(A * jr0, A * jr1) + fminf(B * ir0f, B * ir1f) + 383.5f;
        int ylo = (int)minpy - 2;
        ylo = min(max(ylo, 0), Hh - BP_ROWS);
        shY[tid] = ylo;
    }

    unsigned int mbar_base, ph_base;
    {
        unsigned long long gp = (unsigned long long)mbar;
        asm("{ .reg .u64 t; cvta.to.shared.u64 t, %1; cvt.u32.u64 %0, t; }"
            : "=r"(mbar_base) : "l"(gp));
        gp = (unsigned long long)ph;
        asm("{ .reg .u64 t; cvta.to.shared.u64 t, %1; cvt.u32.u64 %0, t; }"
            : "=r"(ph_base) : "l"(gp));
    }

    if (tid < BP_STAGES)
        asm volatile("mbarrier.init.shared.b64 [%0], %1;"
                     :: "r"(mbar_base + tid * 8), "r"(1) : "memory");
    __syncthreads();     // shY/shA/shB + mbar init visible

    const char* gsrc = (const char*)g_blend2;
    if (tid == 0) {
#pragma unroll
        for (int s = 0; s < BP_STAGES; s++) {
            unsigned int mb = mbar_base + s * 8;
            asm volatile("mbarrier.arrive.expect_tx.shared.b64 _, [%0], %1;"
                         :: "r"(mb), "r"(BP_STAGE_BYTES) : "memory");
#pragma unroll
            for (int h = 0; h < BP_ANG; h++) {
                int a = s * BP_ANG + h;
                asm volatile("cp.async.bulk.shared::cta.global.mbarrier::complete_tx::bytes "
                             "[%0], [%1], %2, [%3];"
                             :: "r"(ph_base + s * BP_STAGE_BYTES + h * BP_ANG_BYTES),
                                "l"(gsrc + ((size_t)a * Hh + shY[a]) * 16),
                                "r"(BP_ANG_BYTES), "r"(mb) : "memory");
            }
        }
    }

    int warp = tid >> 5, lane = tid & 31;
    int lj = lane & 7, li = lane >> 3;        // warp footprint 8j x 4i
    int jgrp = warp & 7, igrp = warp >> 3;
    int j = blockIdx.x * 64 + jgrp * 8 + lj;
    float jr = (float)(j - 256);
    int i_base = blockIdx.y * 32 + igrp * 4 + li;
    float ir[2];
#pragma unroll
    for (int r = 0; r < 2; r++) ir[r] = (float)(i_base + 16 * r - 256);

    float acc[2][8] = {};
    __half2 hones = __float2half2_rn(1.0f);

    for (int rnd = 0; rnd < BP_ROUNDS; rnd++) {
        int b = rnd % BP_STAGES;
        unsigned int mb = mbar_base + b * 8;
        unsigned int parity = (unsigned int)((rnd / BP_STAGES) & 1);
        {
            unsigned int done;
            asm volatile(
                "{\n\t.reg .pred p;\n\t"
                "mbarrier.try_wait.parity.shared.b64 p, [%1], %2;\n\t"
                "selp.b32 %0, 1, 0, p;\n\t}"
                : "=r"(done) : "r"(mb), "r"(parity) : "memory");
            while (!done) {
                asm volatile(
                    "{\n\t.reg .pred p;\n\t"
                    "mbarrier.try_wait.parity.shared.b64 p, [%1], %2, 0x989680;\n\t"
                    "selp.b32 %0, 1, 0, p;\n\t}"
                    : "=r"(done) : "r"(mb), "r"(parity) : "memory");
            }
        }

        const uint4* buf = ph + b * BP_STAGE_U4;

#pragma unroll
        for (int g2 = 0; g2 < 2; g2++) {       // flush half2 partials every 4 angles
            __half2 pacc[2][4];
#pragma unroll
            for (int r = 0; r < 2; r++)
#pragma unroll
                for (int q = 0; q < 4; q++) pacc[r][q] = __float2half2_rn(0.0f);

#pragma unroll
            for (int hh = 0; hh < 4; hh++) {
                int h = g2 * 4 + hh;
                int a = BP_ANG * rnd + h;
                float A = shA[a], B = shB[a];
                int ylo = shY[a];
                float base = fmaf(A, jr, 383.5f);
                const uint4* rows = buf + h * BP_ROWS;
#pragma unroll
                for (int r = 0; r < 2; r++) {
                    float py = fmaf(B, ir[r], base);   // in [21.9, 745.1]
                    int y0 = (int)py;
                    float wy = py - (float)y0;
                    __half2 hw1 = __float2half2_rn(wy);
                    __half2 hw0 = __hsub2(hones, hw1);
                    int yr = y0 - ylo;                 // in [0, 78]
                    uint4 ra = rows[yr];               // warp y-span < 8: conflict-free
                    uint4 rb = rows[yr + 1];
                    const unsigned int* au = (const unsigned int*)&ra;
                    const unsigned int* bu = (const unsigned int*)&rb;
#pragma unroll
                    for (int q = 0; q < 4; q++) {
                        __half2 va = *(__half2*)&au[q];
                        __half2 vb = *(__half2*)&bu[q];
                        pacc[r][q] = __hfma2(va, hw0, pacc[r][q]);
                        pacc[r][q] = __hfma2(vb, hw1, pacc[r][q]);
                    }
                }
            }
#pragma unroll
            for (int r = 0; r < 2; r++)
#pragma unroll
                for (int q = 0; q < 4; q++) {
                    float2 f = __half22float2(pacc[r][q]);
                    acc[r][2 * q]     += f.x;
                    acc[r][2 * q + 1] += f.y;
                }
        }

        __syncthreads();            // all readers of stage b done
        if (tid == 0 && rnd + BP_STAGES < BP_ROUNDS) {
            asm volatile("mbarrier.arrive.expect_tx.shared.b64 _, [%0], %1;"
                         :: "r"(mb), "r"(BP_STAGE_BYTES) : "memory");
#pragma unroll
            for (int h = 0; h < BP_ANG; h++) {
                int a = (rnd + BP_STAGES) * BP_ANG + h;
                asm volatile("cp.async.bulk.shared::cta.global.mbarrier::complete_tx::bytes "
                             "[%0], [%1], %2, [%3];"
                             :: "r"(ph_base + b * BP_STAGE_BYTES + h * BP_ANG_BYTES),
                                "l"(gsrc + ((size_t)a * Hh + shY[a]) * 16),
                                "r"(BP_ANG_BYTES), "r"(mb) : "memory");
            }
        }
    }

    const float SC = (float)(PI_D / 720.0);   // pi / (2W)
#pragma unroll
    for (int r = 0; r < 2; r++) {
        int i = i_base + 16 * r;
#pragma unroll
        for (int n = 0; n < 8; n++)
            out[n * (Dd * Dd) + i * Dd + j] = acc[r][n] * SC;
    }
}

// ---------------- launch ----------------
extern "C" void kernel_launch(void* const* d_in, const int* in_sizes, int n_in,
                              void* d_out, int out_size) {
    (void)in_sizes; (void)n_in; (void)out_size;
    const float* radon = (const float*)d_in[0];
    const float* hG    = (const float*)d_in[1];
    float* out = (float*)d_out;

    const int conv_smem = (320 * SROW + 264) * 4 + 8 * TBW * 2;   // 93,984 B
    cudaFuncSetAttribute(conv_kernel, cudaFuncAttributeMaxDynamicSharedMemorySize, conv_smem);
    const int bp_smem = BP_STAGES * BP_STAGE_BYTES;                // 81,920 B
    cudaFuncSetAttribute(backproj_kernel, cudaFuncAttributeMaxDynamicSharedMemorySize, bp_smem);

    compute_kcp_kernel<<<TAPP, 256>>>(hG);
    params_kernel<<<1, 384>>>();
    rb_kernel<<<dim3(24, 8), 256>>>(radon);
    conv_kernel<<<dim3(45, 12), 256, conv_smem>>>();
    backproj_kernel<<<dim3(8, 16), 1024, bp_smem>>>(out);
}